// round 5
// baseline (speedup 1.0000x reference)
#include <cuda_runtime.h>
#include <cuda_bf16.h>
#include <cstdint>

#define MMAX 200704
#define NB 256

typedef __nv_bfloat16 bf16;

// ---------------- scratch (device globals; no allocation allowed) ----------------
__device__ float g_A[(size_t)MMAX * 128];   // h segment-sum accumulator
__device__ float g_B[(size_t)MMAX * 128];   // x segment-sum accumulator
__device__ float g_C[(size_t)MMAX * 256];   // h1 (conv1 out, fp32 for GN2 stats)
__device__ float g_cnt[MMAX];
__device__ float g_part[2 * NB * 256];
__device__ float g_scale[256];
__device__ float g_shift[256];
__device__ __align__(16) bf16 g_zrow[64];   // stays zero (never written)
// bf16 hi/lo operand planes
__device__ bf16 g_hdh[(size_t)MMAX * 128];
__device__ bf16 g_hdl[(size_t)MMAX * 128];
__device__ bf16 g_xdh[(size_t)MMAX * 128];
__device__ bf16 g_xdl[(size_t)MMAX * 128];
__device__ bf16 g_h2h[(size_t)MMAX * 256];
__device__ bf16 g_h2l[(size_t)MMAX * 256];
__device__ bf16 g_W1h[27 * 256 * 128];      // [k][n][c]
__device__ bf16 g_W1l[27 * 256 * 128];
__device__ bf16 g_W2h[27 * 256 * 256];
__device__ bf16 g_W2l[27 * 256 * 256];
__device__ bf16 g_WSh[256 * 128];
__device__ bf16 g_WSl[256 * 128];

__device__ __forceinline__ float silu_f(float x) { return x / (1.f + __expf(-x)); }

__device__ __forceinline__ uint32_t smem_u32(const void* p) {
    uint32_t a;
    asm("{ .reg .u64 t; cvta.to.shared.u64 t, %1; cvt.u32.u64 %0, t; }" : "=r"(a) : "l"(p));
    return a;
}
__device__ __forceinline__ void cp_async16(uint32_t dst, const void* src) {
    asm volatile("cp.async.cg.shared.global [%0], [%1], 16;" :: "r"(dst), "l"(src));
}
__device__ __forceinline__ void cp_commit() {
    asm volatile("cp.async.commit_group;" ::: "memory");
}
__device__ __forceinline__ void cp_wait0() { asm volatile("cp.async.wait_group 0;" ::: "memory"); }
__device__ __forceinline__ void cp_wait1() { asm volatile("cp.async.wait_group 1;" ::: "memory"); }
__device__ __forceinline__ void cp_wait2() { asm volatile("cp.async.wait_group 2;" ::: "memory"); }
__device__ __forceinline__ void ldmx4(uint32_t* r, uint32_t addr) {
    asm volatile("ldmatrix.sync.aligned.m8n8.x4.shared.b16 {%0,%1,%2,%3}, [%4];"
                 : "=r"(r[0]), "=r"(r[1]), "=r"(r[2]), "=r"(r[3]) : "r"(addr));
}
__device__ __forceinline__ void mma16816(float* d, const uint32_t* a, const uint32_t* b) {
    asm volatile(
        "mma.sync.aligned.m16n8k16.row.col.f32.bf16.bf16.f32 "
        "{%0,%1,%2,%3}, {%4,%5,%6,%7}, {%8,%9}, {%0,%1,%2,%3};"
        : "+f"(d[0]), "+f"(d[1]), "+f"(d[2]), "+f"(d[3])
        : "r"(a[0]), "r"(a[1]), "r"(a[2]), "r"(a[3]), "r"(b[0]), "r"(b[1]));
}

// ---------------- small kernels ----------------
__global__ void zero_kernel(float* p, size_t n) {
    size_t i = (size_t)blockIdx.x * blockDim.x + threadIdx.x;
    size_t s = (size_t)gridDim.x * blockDim.x;
    for (; i < n; i += s) p[i] = 0.f;
}

// float4-vectorized GN stats (per-block per-channel partials; layout part[blk*C+c])
template <int C>
__global__ void gn_stats(const float* __restrict__ x, int n, float* __restrict__ part) {
    const int CG = C / 4;          // channel-groups of 4
    const int RPB = 256 / CG;      // rows per block-iteration
    int tid = threadIdx.x;
    int cg = tid % CG;
    int rsub = tid / CG;
    float4 s = {0, 0, 0, 0}, q = {0, 0, 0, 0};
    for (long r = (long)blockIdx.x * RPB + rsub; r < n; r += (long)gridDim.x * RPB) {
        float4 v = *(const float4*)(x + r * C + cg * 4);
        s.x += v.x; s.y += v.y; s.z += v.z; s.w += v.w;
        q.x += v.x * v.x; q.y += v.y * v.y; q.z += v.z * v.z; q.w += v.w * v.w;
    }
    __shared__ float4 sh[256], sq[256];
    sh[tid] = s; sq[tid] = q;
    __syncthreads();
    if (rsub == 0) {
        for (int j = 1; j < RPB; j++) {
            float4 t = sh[j * CG + cg];
            s.x += t.x; s.y += t.y; s.z += t.z; s.w += t.w;
            t = sq[j * CG + cg];
            q.x += t.x; q.y += t.y; q.z += t.z; q.w += t.w;
        }
        *(float4*)&part[blockIdx.x * C + cg * 4] = s;
        *(float4*)&part[NB * C + blockIdx.x * C + cg * 4] = q;
    }
}

template <int C, int CPG>
__global__ void gn_finalize(const float* __restrict__ part, const float* __restrict__ w,
                            const float* __restrict__ b, float rcount) {
    int c = threadIdx.x;
    float s = 0.f, q = 0.f;
    for (int blk = 0; blk < NB; blk++) {
        s += part[blk * C + c];
        q += part[NB * C + blk * C + c];
    }
    __shared__ float cs[256], cq[256];
    cs[c] = s; cq[c] = q;
    __syncthreads();
    __shared__ float mu[32], rs[32];
    if (c < C / CPG) {
        float S = 0.f, Q = 0.f;
        for (int j = 0; j < CPG; j++) { S += cs[c * CPG + j]; Q += cq[c * CPG + j]; }
        float m = S * rcount;
        float v = Q * rcount - m * m;
        mu[c] = m;
        rs[c] = rsqrtf(v + 1e-5f);
    }
    __syncthreads();
    int g = c / CPG;
    float sc = w[c] * rs[g];
    g_scale[c] = sc;
    g_shift[c] = b[c] - mu[g] * sc;
}

__global__ void downsample_kernel(const float* __restrict__ feats,
                                  const int* __restrict__ seg, int n) {
    long t = (long)blockIdx.x * blockDim.x + threadIdx.x;
    if (t >= (long)n * 32) return;
    int row = (int)(t >> 5);
    int q = (int)(t & 31);
    int c = q * 4;
    int s = seg[row];
    float4 f = *(const float4*)(feats + (long)row * 128 + c);
    float4 sc = *(const float4*)(g_scale + c);
    float4 sh = *(const float4*)(g_shift + c);
    float h0 = silu_f(f.x * sc.x + sh.x);
    float h1 = silu_f(f.y * sc.y + sh.y);
    float h2 = silu_f(f.z * sc.z + sh.z);
    float h3 = silu_f(f.w * sc.w + sh.w);
    float* hp = g_A + (long)s * 128 + c;
    float* xp = g_B + (long)s * 128 + c;
    atomicAdd(hp + 0, h0); atomicAdd(hp + 1, h1);
    atomicAdd(hp + 2, h2); atomicAdd(hp + 3, h3);
    atomicAdd(xp + 0, f.x); atomicAdd(xp + 1, f.y);
    atomicAdd(xp + 2, f.z); atomicAdd(xp + 3, f.w);
    if (q == 0) atomicAdd(g_cnt + s, 1.f);
}

__device__ __forceinline__ void split_store(bf16* ph, bf16* pl, size_t idx, float v) {
    bf16 h = __float2bfloat16(v);
    ph[idx] = h;
    pl[idx] = __float2bfloat16(v - __bfloat162float(h));
}

__global__ void finalize_down(int M) {
    long t = (long)blockIdx.x * blockDim.x + threadIdx.x;
    if (t >= (long)M * 32) return;
    int row = (int)(t >> 5);
    int c = (int)(t & 31) * 4;
    float ic = 1.f / fmaxf(g_cnt[row], 1.f);
    size_t base = (size_t)row * 128 + c;
    float4 va = *(const float4*)(g_A + base);
    float4 vb = *(const float4*)(g_B + base);
    split_store(g_hdh, g_hdl, base + 0, va.x * ic);
    split_store(g_hdh, g_hdl, base + 1, va.y * ic);
    split_store(g_hdh, g_hdl, base + 2, va.z * ic);
    split_store(g_hdh, g_hdl, base + 3, va.w * ic);
    split_store(g_xdh, g_xdl, base + 0, vb.x * ic);
    split_store(g_xdh, g_xdl, base + 1, vb.y * ic);
    split_store(g_xdh, g_xdl, base + 2, vb.z * ic);
    split_store(g_xdh, g_xdl, base + 3, vb.w * ic);
}

__global__ void apply_gn2(int M) {
    long t = (long)blockIdx.x * blockDim.x + threadIdx.x;
    if (t >= (long)M * 64) return;
    int row = (int)(t >> 6);
    int c = (int)(t & 63) * 4;
    size_t base = (size_t)row * 256 + c;
    float4 v = *(const float4*)(g_C + base);
    float4 sc = *(const float4*)(g_scale + c);
    float4 sh = *(const float4*)(g_shift + c);
    split_store(g_h2h, g_h2l, base + 0, silu_f(v.x * sc.x + sh.x));
    split_store(g_h2h, g_h2l, base + 1, silu_f(v.y * sc.y + sh.y));
    split_store(g_h2h, g_h2l, base + 2, silu_f(v.z * sc.z + sh.z));
    split_store(g_h2h, g_h2l, base + 3, silu_f(v.w * sc.w + sh.w));
}

template <int CIN>
__global__ void prep_w(const float* __restrict__ W, bf16* __restrict__ wh,
                       bf16* __restrict__ wl, int total) {
    int idx = blockIdx.x * blockDim.x + threadIdx.x;
    int stride = gridDim.x * blockDim.x;
    for (; idx < total; idx += stride) {
        int c = idx % CIN;
        int n = (idx / CIN) % 256;
        int k = idx / (CIN * 256);
        float v = W[((size_t)k * CIN + c) * 256 + n];
        bf16 h = __float2bfloat16(v);
        wh[idx] = h;
        wl[idx] = __float2bfloat16(v - __bfloat162float(h));
    }
}

// ---------------- HMMA gather-conv, pipelined, 256 threads ----------------------
// CTA 256 thr / 8 warps; tile 64(M) x 256(N); warp grid 2x4 -> 32x64 per warp
// (register budget ~160/thread, no spill at the 255-reg limit).
// Work = uniform chunks (tap, k0) of K=32: A chunk 64x32 (hi+lo, gathered rows,
// 8KB), B chunk 256x32 (hi+lo, 32KB). 64B rows, XOR swizzle u^=(row>>1)&3
// (conflict-free ldmatrix, validated in R4). Triple-buffered cp.async.
// SMEM: A bufs 3x8KB @0, B bufs 3x32KB @24576, nid @122880 (28*64 ints).
static constexpr int CONV_SMEM = 122880 + 28 * 64 * 4;

template <int CIN, bool FUSE_SKIP>
__global__ __launch_bounds__(256, 1) void conv_hmma(
    const bf16* __restrict__ xh, const bf16* __restrict__ xl,
    const bf16* __restrict__ wh, const bf16* __restrict__ wl,
    const bf16* __restrict__ sxh, const bf16* __restrict__ sxl,
    const bf16* __restrict__ swh, const bf16* __restrict__ swl,
    const float* __restrict__ bias, const float* __restrict__ bias2,
    const int* __restrict__ nbr, float* __restrict__ out, int M) {
    extern __shared__ char smem[];
    constexpr int NCH = CIN / 32;
    constexpr int NREG = 27 * NCH;                  // regular chunks
    constexpr int TC = NREG + (FUSE_SKIP ? 4 : 0);  // + skip-tap chunks (cin=128)
    constexpr int NT = FUSE_SKIP ? 28 : 27;
    const uint32_t sbase = smem_u32(smem);
    int* nid = (int*)(smem + 122880);
    const int tid = threadIdx.x;
    const int mbase = blockIdx.x * 64;
    const int lane = tid & 31;
    const int wm = (tid >> 5) >> 2;   // 0..1
    const int wn = (tid >> 5) & 3;    // 0..3

    // prefetch neighbor ids for all taps
    for (int u = tid; u < NT * 64; u += 256) {
        int tap = u >> 6;
        int r = mbase + (u & 63);
        nid[u] = (tap == 27) ? ((r < M) ? r : -1)
                             : ((r < M) ? nbr[(size_t)r * 27 + tap] : -1);
    }
    __syncthreads();

    float d[2][8][4];
#pragma unroll
    for (int a = 0; a < 2; a++)
#pragma unroll
        for (int b = 0; b < 8; b++)
#pragma unroll
            for (int c = 0; c < 4; c++) d[a][b][c] = 0.f;

    // issue chunk i into buffer i%3 (one commit group: A 512 + B 2048 pieces)
    auto issueC = [&](int i) {
        int tap, c0, cin;
        const bf16 *axh, *axl, *bwh, *bwl;
        if (i < NREG) {
            tap = i / NCH; c0 = (i % NCH) * 32; cin = CIN;
            axh = xh; axl = xl;
            bwh = wh + (size_t)tap * 256 * CIN;
            bwl = wl + (size_t)tap * 256 * CIN;
        } else {
            tap = 27; c0 = (i - NREG) * 32; cin = 128;
            axh = sxh; axl = sxl; bwh = swh; bwl = swl;
        }
        const int* nt = nid + tap * 64;
        const uint32_t ab = sbase + (i % 3) * 8192;
        const uint32_t bb = sbase + 24576 + (i % 3) * 32768;
        for (int u = tid; u < 2560; u += 256) {
            if (u < 512) {
                int plane = u >> 8, r = (u >> 2) & 63, q = u & 3;
                int src = nt[r];
                const bf16* sp = (src >= 0)
                    ? ((plane ? axl : axh) + (size_t)src * cin + c0 + q * 8)
                    : (const bf16*)g_zrow;
                cp_async16(ab + plane * 4096 + r * 64 + ((q ^ ((r >> 1) & 3)) << 4), sp);
            } else {
                int v = u - 512;
                int plane = v >> 10, n = (v >> 2) & 255, q = v & 3;
                const bf16* sp = (plane ? bwl : bwh) + (size_t)n * cin + c0 + q * 8;
                cp_async16(bb + plane * 16384 + n * 64 + ((q ^ ((n >> 1) & 3)) << 4), sp);
            }
        }
        cp_commit();
    };

    issueC(0);
    if (TC > 1) issueC(1);
    if (TC > 2) issueC(2);

    for (int i = 0; i < TC; i++) {
        int ahead = TC - 1 - i;  // groups newer than chunk i (committed so far)
        if (ahead >= 2) cp_wait2();
        else if (ahead == 1) cp_wait1();
        else cp_wait0();
        __syncthreads();

        const uint32_t ab = sbase + (i % 3) * 8192;
        const uint32_t bb = sbase + 24576 + (i % 3) * 32768;
#pragma unroll
        for (int ks = 0; ks < 2; ks++) {
            uint32_t ah[2][4], al[2][4];
            const int u = ks * 2 + ((lane >> 4) & 1);
#pragma unroll
            for (int mt = 0; mt < 2; mt++) {
                int row = wm * 32 + mt * 16 + (lane & 15);
                uint32_t ad = ab + row * 64 + ((u ^ ((row >> 1) & 3)) << 4);
                ldmx4(ah[mt], ad);
                ldmx4(al[mt], ad + 4096);
            }
            const int brow = (lane & 7) + ((lane & 16) ? 8 : 0);
            const int bu = ks * 2 + ((lane >> 3) & 1);
#pragma unroll
            for (int p = 0; p < 4; p++) {
                int n = wn * 64 + p * 16 + brow;
                uint32_t bd = bb + n * 64 + ((bu ^ ((n >> 1) & 3)) << 4);
                uint32_t bh[4], bl[4];
                ldmx4(bh, bd);
                ldmx4(bl, bd + 16384);
#pragma unroll
                for (int mt = 0; mt < 2; mt++) {
                    mma16816(d[mt][2 * p + 0], ah[mt], &bh[0]);
                    mma16816(d[mt][2 * p + 1], ah[mt], &bh[2]);
                    mma16816(d[mt][2 * p + 0], ah[mt], &bl[0]);
                    mma16816(d[mt][2 * p + 1], ah[mt], &bl[2]);
                    mma16816(d[mt][2 * p + 0], al[mt], &bh[0]);
                    mma16816(d[mt][2 * p + 1], al[mt], &bh[2]);
                }
            }
        }
        __syncthreads();
        if (i + 3 < TC) issueC(i + 3);
    }

    // epilogue: direct global stores
#pragma unroll
    for (int mt = 0; mt < 2; mt++) {
        int r0 = mbase + wm * 32 + mt * 16 + lane / 4;
#pragma unroll
        for (int t = 0; t < 8; t++) {
            int gc = wn * 64 + t * 8 + (lane % 4) * 2;
            float bx = bias[gc], by = bias[gc + 1];
            if (FUSE_SKIP) { bx += bias2[gc]; by += bias2[gc + 1]; }
            if (r0 < M) {
                float2 v = {d[mt][t][0] + bx, d[mt][t][1] + by};
                *(float2*)(out + (size_t)r0 * 256 + gc) = v;
            }
            if (r0 + 8 < M) {
                float2 v = {d[mt][t][2] + bx, d[mt][t][3] + by};
                *(float2*)(out + (size_t)(r0 + 8) * 256 + gc) = v;
            }
        }
    }
}

// ---------------- launch ----------------
extern "C" void kernel_launch(void* const* d_in, const int* in_sizes, int n_in,
                              void* d_out, int out_size) {
    const float* feats = (const float*)d_in[0];
    const float* gn1_w = (const float*)d_in[1];
    const float* gn1_b = (const float*)d_in[2];
    const float* W1    = (const float*)d_in[3];
    const float* b1    = (const float*)d_in[4];
    const float* gn2_w = (const float*)d_in[5];
    const float* gn2_b = (const float*)d_in[6];
    const float* W2    = (const float*)d_in[7];
    const float* b2    = (const float*)d_in[8];
    const float* Wskip = (const float*)d_in[9];
    const float* bskip = (const float*)d_in[10];
    const int* pool_seg = (const int*)d_in[11];
    const int* nbr_idx  = (const int*)d_in[12];
    float* out = (float*)d_out;

    int N = in_sizes[0] / 128;
    int M = in_sizes[12] / 27;

    float *A, *B, *C, *cnt, *part;
    cudaGetSymbolAddress((void**)&A, g_A);
    cudaGetSymbolAddress((void**)&B, g_B);
    cudaGetSymbolAddress((void**)&C, g_C);
    cudaGetSymbolAddress((void**)&cnt, g_cnt);
    cudaGetSymbolAddress((void**)&part, g_part);
    bf16 *hdh, *hdl, *xdh, *xdl, *h2h, *h2l, *W1h, *W1l, *W2h, *W2l, *WSh, *WSl;
    cudaGetSymbolAddress((void**)&hdh, g_hdh);
    cudaGetSymbolAddress((void**)&hdl, g_hdl);
    cudaGetSymbolAddress((void**)&xdh, g_xdh);
    cudaGetSymbolAddress((void**)&xdl, g_xdl);
    cudaGetSymbolAddress((void**)&h2h, g_h2h);
    cudaGetSymbolAddress((void**)&h2l, g_h2l);
    cudaGetSymbolAddress((void**)&W1h, g_W1h);
    cudaGetSymbolAddress((void**)&W1l, g_W1l);
    cudaGetSymbolAddress((void**)&W2h, g_W2h);
    cudaGetSymbolAddress((void**)&W2l, g_W2l);
    cudaGetSymbolAddress((void**)&WSh, g_WSh);
    cudaGetSymbolAddress((void**)&WSl, g_WSl);

    cudaFuncSetAttribute(conv_hmma<128, false>,
                         cudaFuncAttributeMaxDynamicSharedMemorySize, CONV_SMEM);
    cudaFuncSetAttribute(conv_hmma<256, true>,
                         cudaFuncAttributeMaxDynamicSharedMemorySize, CONV_SMEM);

    // zero atomic accumulators (graph replays -> re-zero every launch)
    zero_kernel<<<4096, 256>>>(A, (size_t)M * 128);
    zero_kernel<<<4096, 256>>>(B, (size_t)M * 128);
    zero_kernel<<<256, 256>>>(cnt, (size_t)M);

    // weight transpose + bf16 hi/lo split
    prep_w<128><<<1024, 256>>>(W1, W1h, W1l, 27 * 256 * 128);
    prep_w<256><<<2048, 256>>>(W2, W2h, W2l, 27 * 256 * 256);
    prep_w<128><<<128, 256>>>(Wskip, WSh, WSl, 256 * 128);

    // GN1 stats + finalize
    gn_stats<128><<<NB, 256>>>(feats, N, part);
    gn_finalize<128, 4><<<1, 128>>>(part, gn1_w, gn1_b, 1.f / ((float)N * 4.f));

    // GN1 apply + SiLU + segment sums; then means + hi/lo planes
    long dthreads = (long)N * 32;
    downsample_kernel<<<(int)((dthreads + 255) / 256), 256>>>(feats, pool_seg, N);
    long fthreads = (long)M * 32;
    finalize_down<<<(int)((fthreads + 255) / 256), 256>>>(M);

    int nconv = (M + 63) / 64;

    // conv1: h1 = conv(h_d, W1) + b1
    conv_hmma<128, false><<<nconv, 256, CONV_SMEM>>>(
        hdh, hdl, W1h, W1l, nullptr, nullptr, nullptr, nullptr,
        b1, nullptr, nbr_idx, C, M);

    // GN2 stats + finalize + apply (emits h2 hi/lo planes)
    gn_stats<256><<<NB, 256>>>(C, M, part);
    gn_finalize<256, 8><<<1, 256>>>(part, gn2_w, gn2_b, 1.f / ((float)M * 8.f));
    long athreads = (long)M * 64;
    apply_gn2<<<(int)((athreads + 255) / 256), 256>>>(M);

    // conv2 + fused skip: out = conv(h2, W2) + b2 + x_d @ Wskip + bskip
    conv_hmma<256, true><<<nconv, 256, CONV_SMEM>>>(
        h2h, h2l, W2h, W2l, xdh, xdl, WSh, WSl,
        b2, bskip, nbr_idx, out, M);
}

// round 6
// speedup vs baseline: 3.9949x; 3.9949x over previous
#include <cuda_runtime.h>
#include <cuda_bf16.h>
#include <cstdint>

#define MMAX 200704
#define NB 256

typedef __nv_bfloat16 bf16;

// ---------------- scratch (device globals; no allocation allowed) ----------------
__device__ float g_A[(size_t)MMAX * 128];   // h segment-sum accumulator
__device__ float g_B[(size_t)MMAX * 128];   // x segment-sum accumulator
__device__ float g_C[(size_t)MMAX * 256];   // h1 (conv1 out, fp32 for GN2 stats)
__device__ float g_cnt[MMAX];
__device__ float g_part[2 * NB * 256];
__device__ float g_scale[256];
__device__ float g_shift[256];
__device__ __align__(16) bf16 g_zrow[64];   // safe src for zero-fill cp.async
// bf16 hi/lo operand planes
__device__ bf16 g_hdh[(size_t)MMAX * 128];
__device__ bf16 g_hdl[(size_t)MMAX * 128];
__device__ bf16 g_xdh[(size_t)MMAX * 128];
__device__ bf16 g_xdl[(size_t)MMAX * 128];
__device__ bf16 g_h2h[(size_t)MMAX * 256];
__device__ bf16 g_h2l[(size_t)MMAX * 256];
__device__ bf16 g_W1h[27 * 256 * 128];      // [k][n][c]
__device__ bf16 g_W1l[27 * 256 * 128];
__device__ bf16 g_W2h[27 * 256 * 256];
__device__ bf16 g_W2l[27 * 256 * 256];
__device__ bf16 g_WSh[256 * 128];
__device__ bf16 g_WSl[256 * 128];

__device__ __forceinline__ float silu_f(float x) { return x / (1.f + __expf(-x)); }

__device__ __forceinline__ uint32_t smem_u32(const void* p) {
    uint32_t a;
    asm("{ .reg .u64 t; cvta.to.shared.u64 t, %1; cvt.u32.u64 %0, t; }" : "=r"(a) : "l"(p));
    return a;
}
__device__ __forceinline__ void cp_async16(uint32_t dst, const void* src) {
    asm volatile("cp.async.cg.shared.global [%0], [%1], 16;" :: "r"(dst), "l"(src));
}
// zero-fill form: src-size=0 -> writes 16 zero bytes, NO global read issued
__device__ __forceinline__ void cp_async16z(uint32_t dst, const void* src, uint32_t srcsz) {
    asm volatile("cp.async.cg.shared.global [%0], [%1], 16, %2;"
                 :: "r"(dst), "l"(src), "r"(srcsz));
}
__device__ __forceinline__ void cp_commit() {
    asm volatile("cp.async.commit_group;" ::: "memory");
}
__device__ __forceinline__ void cp_wait0() { asm volatile("cp.async.wait_group 0;" ::: "memory"); }
__device__ __forceinline__ void cp_wait1() { asm volatile("cp.async.wait_group 1;" ::: "memory"); }
__device__ __forceinline__ void cp_wait2() { asm volatile("cp.async.wait_group 2;" ::: "memory"); }
__device__ __forceinline__ void ldmx4(uint32_t* r, uint32_t addr) {
    asm volatile("ldmatrix.sync.aligned.m8n8.x4.shared.b16 {%0,%1,%2,%3}, [%4];"
                 : "=r"(r[0]), "=r"(r[1]), "=r"(r[2]), "=r"(r[3]) : "r"(addr));
}
__device__ __forceinline__ void mma16816(float* d, const uint32_t* a, const uint32_t* b) {
    asm volatile(
        "mma.sync.aligned.m16n8k16.row.col.f32.bf16.bf16.f32 "
        "{%0,%1,%2,%3}, {%4,%5,%6,%7}, {%8,%9}, {%0,%1,%2,%3};"
        : "+f"(d[0]), "+f"(d[1]), "+f"(d[2]), "+f"(d[3])
        : "r"(a[0]), "r"(a[1]), "r"(a[2]), "r"(a[3]), "r"(b[0]), "r"(b[1]));
}

// ---------------- small kernels ----------------
__global__ void zero_kernel(float* p, size_t n) {
    size_t i = (size_t)blockIdx.x * blockDim.x + threadIdx.x;
    size_t s = (size_t)gridDim.x * blockDim.x;
    for (; i < n; i += s) p[i] = 0.f;
}

// float4-vectorized GN stats (per-block per-channel partials; layout part[blk*C+c])
template <int C>
__global__ void gn_stats(const float* __restrict__ x, int n, float* __restrict__ part) {
    const int CG = C / 4;          // channel-groups of 4
    const int RPB = 256 / CG;      // rows per block-iteration
    int tid = threadIdx.x;
    int cg = tid % CG;
    int rsub = tid / CG;
    float4 s = {0, 0, 0, 0}, q = {0, 0, 0, 0};
    for (long r = (long)blockIdx.x * RPB + rsub; r < n; r += (long)gridDim.x * RPB) {
        float4 v = *(const float4*)(x + r * C + cg * 4);
        s.x += v.x; s.y += v.y; s.z += v.z; s.w += v.w;
        q.x += v.x * v.x; q.y += v.y * v.y; q.z += v.z * v.z; q.w += v.w * v.w;
    }
    __shared__ float4 sh[256], sq[256];
    sh[tid] = s; sq[tid] = q;
    __syncthreads();
    if (rsub == 0) {
        for (int j = 1; j < RPB; j++) {
            float4 t = sh[j * CG + cg];
            s.x += t.x; s.y += t.y; s.z += t.z; s.w += t.w;
            t = sq[j * CG + cg];
            q.x += t.x; q.y += t.y; q.z += t.z; q.w += t.w;
        }
        *(float4*)&part[blockIdx.x * C + cg * 4] = s;
        *(float4*)&part[NB * C + blockIdx.x * C + cg * 4] = q;
    }
}

template <int C, int CPG>
__global__ void gn_finalize(const float* __restrict__ part, const float* __restrict__ w,
                            const float* __restrict__ b, float rcount) {
    int c = threadIdx.x;
    float s = 0.f, q = 0.f;
    for (int blk = 0; blk < NB; blk++) {
        s += part[blk * C + c];
        q += part[NB * C + blk * C + c];
    }
    __shared__ float cs[256], cq[256];
    cs[c] = s; cq[c] = q;
    __syncthreads();
    __shared__ float mu[32], rs[32];
    if (c < C / CPG) {
        float S = 0.f, Q = 0.f;
        for (int j = 0; j < CPG; j++) { S += cs[c * CPG + j]; Q += cq[c * CPG + j]; }
        float m = S * rcount;
        float v = Q * rcount - m * m;
        mu[c] = m;
        rs[c] = rsqrtf(v + 1e-5f);
    }
    __syncthreads();
    int g = c / CPG;
    float sc = w[c] * rs[g];
    g_scale[c] = sc;
    g_shift[c] = b[c] - mu[g] * sc;
}

__global__ void downsample_kernel(const float* __restrict__ feats,
                                  const int* __restrict__ seg, int n) {
    long t = (long)blockIdx.x * blockDim.x + threadIdx.x;
    if (t >= (long)n * 32) return;
    int row = (int)(t >> 5);
    int q = (int)(t & 31);
    int c = q * 4;
    int s = seg[row];
    float4 f = *(const float4*)(feats + (long)row * 128 + c);
    float4 sc = *(const float4*)(g_scale + c);
    float4 sh = *(const float4*)(g_shift + c);
    float h0 = silu_f(f.x * sc.x + sh.x);
    float h1 = silu_f(f.y * sc.y + sh.y);
    float h2 = silu_f(f.z * sc.z + sh.z);
    float h3 = silu_f(f.w * sc.w + sh.w);
    float* hp = g_A + (long)s * 128 + c;
    float* xp = g_B + (long)s * 128 + c;
    atomicAdd(hp + 0, h0); atomicAdd(hp + 1, h1);
    atomicAdd(hp + 2, h2); atomicAdd(hp + 3, h3);
    atomicAdd(xp + 0, f.x); atomicAdd(xp + 1, f.y);
    atomicAdd(xp + 2, f.z); atomicAdd(xp + 3, f.w);
    if (q == 0) atomicAdd(g_cnt + s, 1.f);
}

__device__ __forceinline__ void split_store(bf16* ph, bf16* pl, size_t idx, float v) {
    bf16 h = __float2bfloat16(v);
    ph[idx] = h;
    pl[idx] = __float2bfloat16(v - __bfloat162float(h));
}

__global__ void finalize_down(int M) {
    long t = (long)blockIdx.x * blockDim.x + threadIdx.x;
    if (t >= (long)M * 32) return;
    int row = (int)(t >> 5);
    int c = (int)(t & 31) * 4;
    float ic = 1.f / fmaxf(g_cnt[row], 1.f);
    size_t base = (size_t)row * 128 + c;
    float4 va = *(const float4*)(g_A + base);
    float4 vb = *(const float4*)(g_B + base);
    split_store(g_hdh, g_hdl, base + 0, va.x * ic);
    split_store(g_hdh, g_hdl, base + 1, va.y * ic);
    split_store(g_hdh, g_hdl, base + 2, va.z * ic);
    split_store(g_hdh, g_hdl, base + 3, va.w * ic);
    split_store(g_xdh, g_xdl, base + 0, vb.x * ic);
    split_store(g_xdh, g_xdl, base + 1, vb.y * ic);
    split_store(g_xdh, g_xdl, base + 2, vb.z * ic);
    split_store(g_xdh, g_xdl, base + 3, vb.w * ic);
}

__global__ void apply_gn2(int M) {
    long t = (long)blockIdx.x * blockDim.x + threadIdx.x;
    if (t >= (long)M * 64) return;
    int row = (int)(t >> 6);
    int c = (int)(t & 63) * 4;
    size_t base = (size_t)row * 256 + c;
    float4 v = *(const float4*)(g_C + base);
    float4 sc = *(const float4*)(g_scale + c);
    float4 sh = *(const float4*)(g_shift + c);
    split_store(g_h2h, g_h2l, base + 0, silu_f(v.x * sc.x + sh.x));
    split_store(g_h2h, g_h2l, base + 1, silu_f(v.y * sc.y + sh.y));
    split_store(g_h2h, g_h2l, base + 2, silu_f(v.z * sc.z + sh.z));
    split_store(g_h2h, g_h2l, base + 3, silu_f(v.w * sc.w + sh.w));
}

template <int CIN>
__global__ void prep_w(const float* __restrict__ W, bf16* __restrict__ wh,
                       bf16* __restrict__ wl, int total) {
    int idx = blockIdx.x * blockDim.x + threadIdx.x;
    int stride = gridDim.x * blockDim.x;
    for (; idx < total; idx += stride) {
        int c = idx % CIN;
        int n = (idx / CIN) % 256;
        int k = idx / (CIN * 256);
        float v = W[((size_t)k * CIN + c) * 256 + n];
        bf16 h = __float2bfloat16(v);
        wh[idx] = h;
        wl[idx] = __float2bfloat16(v - __bfloat162float(h));
    }
}

// ---------------- HMMA gather-conv, pipelined, 256 threads ----------------------
// CTA 256 thr / 8 warps; tile 64(M) x 256(N); warp grid 2x4 -> 32x64 per warp.
// Uniform chunks (tap, k0=32): A 64x32 hi+lo (8KB, gathered; missing rows use
// cp.async src-size=0 zero-fill -> NO global traffic), B 256x32 hi+lo (32KB).
// 64B rows, XOR swizzle u^=(row>>1)&3 (conflict-free). Triple-buffered cp.async.
// SMEM: A bufs 3x8KB @0, B bufs 3x32KB @24576, nid @122880 (28*64 ints).
static constexpr int CONV_SMEM = 122880 + 28 * 64 * 4;

template <int CIN, bool FUSE_SKIP>
__global__ __launch_bounds__(256, 1) void conv_hmma(
    const bf16* __restrict__ xh, const bf16* __restrict__ xl,
    const bf16* __restrict__ wh, const bf16* __restrict__ wl,
    const bf16* __restrict__ sxh, const bf16* __restrict__ sxl,
    const bf16* __restrict__ swh, const bf16* __restrict__ swl,
    const float* __restrict__ bias, const float* __restrict__ bias2,
    const int* __restrict__ nbr, float* __restrict__ out, int M) {
    extern __shared__ char smem[];
    constexpr int NCH = CIN / 32;
    constexpr int NREG = 27 * NCH;                  // regular chunks
    constexpr int TC = NREG + (FUSE_SKIP ? 4 : 0);  // + skip-tap chunks (cin=128)
    constexpr int NT = FUSE_SKIP ? 28 : 27;
    const uint32_t sbase = smem_u32(smem);
    int* nid = (int*)(smem + 122880);
    const int tid = threadIdx.x;
    const int mbase = blockIdx.x * 64;
    const int lane = tid & 31;
    const int wm = (tid >> 5) >> 2;   // 0..1
    const int wn = (tid >> 5) & 3;    // 0..3

    // prefetch neighbor ids for all taps
    for (int u = tid; u < NT * 64; u += 256) {
        int tap = u >> 6;
        int r = mbase + (u & 63);
        nid[u] = (tap == 27) ? ((r < M) ? r : -1)
                             : ((r < M) ? nbr[(size_t)r * 27 + tap] : -1);
    }
    __syncthreads();

    float d[2][8][4];
#pragma unroll
    for (int a = 0; a < 2; a++)
#pragma unroll
        for (int b = 0; b < 8; b++)
#pragma unroll
            for (int c = 0; c < 4; c++) d[a][b][c] = 0.f;

    // issue chunk i into buffer i%3 (one commit group: A 512 + B 2048 pieces)
    auto issueC = [&](int i) {
        int tap, c0, cin;
        const bf16 *axh, *axl, *bwh, *bwl;
        if (i < NREG) {
            tap = i / NCH; c0 = (i % NCH) * 32; cin = CIN;
            axh = xh; axl = xl;
            bwh = wh + (size_t)tap * 256 * CIN;
            bwl = wl + (size_t)tap * 256 * CIN;
        } else {
            tap = 27; c0 = (i - NREG) * 32; cin = 128;
            axh = sxh; axl = sxl; bwh = swh; bwl = swl;
        }
        const int* nt = nid + tap * 64;
        const uint32_t ab = sbase + (i % 3) * 8192;
        const uint32_t bb = sbase + 24576 + (i % 3) * 32768;
        for (int u = tid; u < 2560; u += 256) {
            if (u < 512) {
                int plane = u >> 8, r = (u >> 2) & 63, q = u & 3;
                int src = nt[r];
                // missing neighbor: src-size=0 -> zero-fill, no global read
                const bf16* sp = (src >= 0)
                    ? ((plane ? axl : axh) + (size_t)src * cin + c0 + q * 8)
                    : (const bf16*)g_zrow;
                cp_async16z(ab + plane * 4096 + r * 64 + ((q ^ ((r >> 1) & 3)) << 4),
                            sp, (src >= 0) ? 16u : 0u);
            } else {
                int v = u - 512;
                int plane = v >> 10, n = (v >> 2) & 255, q = v & 3;
                const bf16* sp = (plane ? bwl : bwh) + (size_t)n * cin + c0 + q * 8;
                cp_async16(bb + plane * 16384 + n * 64 + ((q ^ ((n >> 1) & 3)) << 4), sp);
            }
        }
        cp_commit();
    };

    issueC(0);
    if (TC > 1) issueC(1);
    if (TC > 2) issueC(2);

    for (int i = 0; i < TC; i++) {
        int ahead = TC - 1 - i;  // committed groups newer than chunk i
        if (ahead >= 2) cp_wait2();
        else if (ahead == 1) cp_wait1();
        else cp_wait0();
        __syncthreads();

        const uint32_t ab = sbase + (i % 3) * 8192;
        const uint32_t bb = sbase + 24576 + (i % 3) * 32768;
#pragma unroll
        for (int ks = 0; ks < 2; ks++) {
            uint32_t ah[2][4], al[2][4];
            const int u = ks * 2 + ((lane >> 4) & 1);
#pragma unroll
            for (int mt = 0; mt < 2; mt++) {
                int row = wm * 32 + mt * 16 + (lane & 15);
                uint32_t ad = ab + row * 64 + ((u ^ ((row >> 1) & 3)) << 4);
                ldmx4(ah[mt], ad);
                ldmx4(al[mt], ad + 4096);
            }
            const int brow = (lane & 7) + ((lane & 16) ? 8 : 0);
            const int bu = ks * 2 + ((lane >> 3) & 1);
#pragma unroll
            for (int p = 0; p < 4; p++) {
                int n = wn * 64 + p * 16 + brow;
                uint32_t bd = bb + n * 64 + ((bu ^ ((n >> 1) & 3)) << 4);
                uint32_t bh[4], bl[4];
                ldmx4(bh, bd);
                ldmx4(bl, bd + 16384);
#pragma unroll
                for (int mt = 0; mt < 2; mt++) {
                    mma16816(d[mt][2 * p + 0], ah[mt], &bh[0]);
                    mma16816(d[mt][2 * p + 1], ah[mt], &bh[2]);
                    mma16816(d[mt][2 * p + 0], ah[mt], &bl[0]);
                    mma16816(d[mt][2 * p + 1], ah[mt], &bl[2]);
                    mma16816(d[mt][2 * p + 0], al[mt], &bh[0]);
                    mma16816(d[mt][2 * p + 1], al[mt], &bh[2]);
                }
            }
        }
        __syncthreads();
        if (i + 3 < TC) issueC(i + 3);
    }

    // epilogue: direct global stores
#pragma unroll
    for (int mt = 0; mt < 2; mt++) {
        int r0 = mbase + wm * 32 + mt * 16 + lane / 4;
#pragma unroll
        for (int t = 0; t < 8; t++) {
            int gc = wn * 64 + t * 8 + (lane % 4) * 2;
            float bx = bias[gc], by = bias[gc + 1];
            if (FUSE_SKIP) { bx += bias2[gc]; by += bias2[gc + 1]; }
            if (r0 < M) {
                float2 v = {d[mt][t][0] + bx, d[mt][t][1] + by};
                *(float2*)(out + (size_t)r0 * 256 + gc) = v;
            }
            if (r0 + 8 < M) {
                float2 v = {d[mt][t][2] + bx, d[mt][t][3] + by};
                *(float2*)(out + (size_t)(r0 + 8) * 256 + gc) = v;
            }
        }
    }
}

// ---------------- launch ----------------
extern "C" void kernel_launch(void* const* d_in, const int* in_sizes, int n_in,
                              void* d_out, int out_size) {
    const float* feats = (const float*)d_in[0];
    const float* gn1_w = (const float*)d_in[1];
    const float* gn1_b = (const float*)d_in[2];
    const float* W1    = (const float*)d_in[3];
    const float* b1    = (const float*)d_in[4];
    const float* gn2_w = (const float*)d_in[5];
    const float* gn2_b = (const float*)d_in[6];
    const float* W2    = (const float*)d_in[7];
    const float* b2    = (const float*)d_in[8];
    const float* Wskip = (const float*)d_in[9];
    const float* bskip = (const float*)d_in[10];
    const int* pool_seg = (const int*)d_in[11];
    const int* nbr_idx  = (const int*)d_in[12];
    float* out = (float*)d_out;

    int N = in_sizes[0] / 128;
    int M = in_sizes[12] / 27;

    float *A, *B, *C, *cnt, *part;
    cudaGetSymbolAddress((void**)&A, g_A);
    cudaGetSymbolAddress((void**)&B, g_B);
    cudaGetSymbolAddress((void**)&C, g_C);
    cudaGetSymbolAddress((void**)&cnt, g_cnt);
    cudaGetSymbolAddress((void**)&part, g_part);
    bf16 *hdh, *hdl, *xdh, *xdl, *h2h, *h2l, *W1h, *W1l, *W2h, *W2l, *WSh, *WSl;
    cudaGetSymbolAddress((void**)&hdh, g_hdh);
    cudaGetSymbolAddress((void**)&hdl, g_hdl);
    cudaGetSymbolAddress((void**)&xdh, g_xdh);
    cudaGetSymbolAddress((void**)&xdl, g_xdl);
    cudaGetSymbolAddress((void**)&h2h, g_h2h);
    cudaGetSymbolAddress((void**)&h2l, g_h2l);
    cudaGetSymbolAddress((void**)&W1h, g_W1h);
    cudaGetSymbolAddress((void**)&W1l, g_W1l);
    cudaGetSymbolAddress((void**)&W2h, g_W2h);
    cudaGetSymbolAddress((void**)&W2l, g_W2l);
    cudaGetSymbolAddress((void**)&WSh, g_WSh);
    cudaGetSymbolAddress((void**)&WSl, g_WSl);

    cudaFuncSetAttribute(conv_hmma<128, false>,
                         cudaFuncAttributeMaxDynamicSharedMemorySize, CONV_SMEM);
    cudaFuncSetAttribute(conv_hmma<256, true>,
                         cudaFuncAttributeMaxDynamicSharedMemorySize, CONV_SMEM);

    // zero atomic accumulators (graph replays -> re-zero every launch)
    zero_kernel<<<4096, 256>>>(A, (size_t)M * 128);
    zero_kernel<<<4096, 256>>>(B, (size_t)M * 128);
    zero_kernel<<<256, 256>>>(cnt, (size_t)M);

    // weight transpose + bf16 hi/lo split
    prep_w<128><<<1024, 256>>>(W1, W1h, W1l, 27 * 256 * 128);
    prep_w<256><<<2048, 256>>>(W2, W2h, W2l, 27 * 256 * 256);
    prep_w<128><<<128, 256>>>(Wskip, WSh, WSl, 256 * 128);

    // GN1 stats + finalize
    gn_stats<128><<<NB, 256>>>(feats, N, part);
    gn_finalize<128, 4><<<1, 128>>>(part, gn1_w, gn1_b, 1.f / ((float)N * 4.f));

    // GN1 apply + SiLU + segment sums; then means + hi/lo planes
    long dthreads = (long)N * 32;
    downsample_kernel<<<(int)((dthreads + 255) / 256), 256>>>(feats, pool_seg, N);
    long fthreads = (long)M * 32;
    finalize_down<<<(int)((fthreads + 255) / 256), 256>>>(M);

    int nconv = (M + 63) / 64;

    // conv1: h1 = conv(h_d, W1) + b1
    conv_hmma<128, false><<<nconv, 256, CONV_SMEM>>>(
        hdh, hdl, W1h, W1l, nullptr, nullptr, nullptr, nullptr,
        b1, nullptr, nbr_idx, C, M);

    // GN2 stats + finalize + apply (emits h2 hi/lo planes)
    gn_stats<256><<<NB, 256>>>(C, M, part);
    gn_finalize<256, 8><<<1, 256>>>(part, gn2_w, gn2_b, 1.f / ((float)M * 8.f));
    long athreads = (long)M * 64;
    apply_gn2<<<(int)((athreads + 255) / 256), 256>>>(M);

    // conv2 + fused skip: out = conv(h2, W2) + b2 + x_d @ Wskip + bskip
    conv_hmma<256, true><<<nconv, 256, CONV_SMEM>>>(
        h2h, h2l, W2h, W2l, xdh, xdl, WSh, WSl,
        b2, bskip, nbr_idx, out, M);
}

// round 7
// speedup vs baseline: 5.1505x; 1.2893x over previous
#include <cuda_runtime.h>
#include <cuda_bf16.h>
#include <cstdint>

#define MMAX 200704
#define NB 256

typedef __nv_bfloat16 bf16;

// ---------------- scratch (device globals; no allocation allowed) ----------------
__device__ float g_A[(size_t)MMAX * 128];   // h segment-sum accumulator
__device__ float g_B[(size_t)MMAX * 128];   // x segment-sum accumulator
__device__ float g_C[(size_t)MMAX * 256];   // h1 (conv1 out, fp32 for GN2 stats)
__device__ float g_cnt[MMAX];
__device__ float g_part[2 * NB * 256];
__device__ float g_scale[256];
__device__ float g_shift[256];
__device__ __align__(16) bf16 g_zrow[64];   // safe src for zero-fill cp.async
// bf16 hi/lo operand planes
__device__ bf16 g_hdh[(size_t)MMAX * 128];
__device__ bf16 g_hdl[(size_t)MMAX * 128];
__device__ bf16 g_xdh[(size_t)MMAX * 128];
__device__ bf16 g_xdl[(size_t)MMAX * 128];
__device__ bf16 g_h2h[(size_t)MMAX * 256];
__device__ bf16 g_h2l[(size_t)MMAX * 256];
// weights: chunked+pre-swizzled layout [tap*NCH+ch][n=256][32] (16KB blocks)
__device__ __align__(16) bf16 g_W1h[27 * 256 * 128];
__device__ __align__(16) bf16 g_W1l[27 * 256 * 128];
__device__ __align__(16) bf16 g_W2h[27 * 256 * 256];
__device__ __align__(16) bf16 g_W2l[27 * 256 * 256];
__device__ __align__(16) bf16 g_WSh[256 * 128];
__device__ __align__(16) bf16 g_WSl[256 * 128];

__device__ __forceinline__ float silu_f(float x) { return x / (1.f + __expf(-x)); }

__device__ __forceinline__ uint32_t smem_u32(const void* p) {
    uint32_t a;
    asm("{ .reg .u64 t; cvta.to.shared.u64 t, %1; cvt.u32.u64 %0, t; }" : "=r"(a) : "l"(p));
    return a;
}
// zero-fill form: src-size=0 -> writes 16 zero bytes, NO global read issued
__device__ __forceinline__ void cp_async16z(uint32_t dst, const void* src, uint32_t srcsz) {
    asm volatile("cp.async.cg.shared.global [%0], [%1], 16, %2;"
                 :: "r"(dst), "l"(src), "r"(srcsz));
}
__device__ __forceinline__ void cp_commit() {
    asm volatile("cp.async.commit_group;" ::: "memory");
}
__device__ __forceinline__ void cp_wait0() { asm volatile("cp.async.wait_group 0;" ::: "memory"); }
__device__ __forceinline__ void cp_wait1() { asm volatile("cp.async.wait_group 1;" ::: "memory"); }
__device__ __forceinline__ void cp_wait2() { asm volatile("cp.async.wait_group 2;" ::: "memory"); }
// bulk g2s copy completing on an mbarrier (sm_90 base feature)
__device__ __forceinline__ void cp_bulk_g2s(uint32_t dst, const void* src, uint32_t bytes,
                                            uint32_t mbar) {
    asm volatile(
        "cp.async.bulk.shared::cta.global.mbarrier::complete_tx::bytes [%0], [%1], %2, [%3];"
        :: "r"(dst), "l"(src), "r"(bytes), "r"(mbar) : "memory");
}
#define MBARRIER_INIT(addr, cnt) \
    asm volatile("mbarrier.init.shared.b64 [%0], %1;" :: "r"(addr), "r"(cnt) : "memory")
#define MBAR_ARRIVE_EXPECT(m, b) \
    asm volatile("mbarrier.arrive.expect_tx.shared.b64 _, [%0], %1;" :: "r"(m), "r"(b) : "memory")
#define MBARRIER_WAIT_PARITY(addr, par) do {                                           \
    uint32_t _m = (addr); uint32_t _p = (par); uint32_t _done;                         \
    asm volatile("{\n\t.reg .pred p;\n\t"                                              \
        "mbarrier.try_wait.parity.acquire.cta.shared::cta.b64 p, [%1], %2;\n\t"        \
        "selp.b32 %0, 1, 0, p;\n\t}" : "=r"(_done) : "r"(_m), "r"(_p) : "memory");     \
    if (!_done) {                                                                      \
        asm volatile("{\n\t.reg .pred P1;\n\tWL_%=:\n\t"                               \
            "mbarrier.try_wait.parity.acquire.cta.shared::cta.b64 P1, [%0], %1, 0x989680;\n\t" \
            "@P1 bra.uni WD_%=;\n\tbra.uni WL_%=;\n\tWD_%=:\n\t}"                      \
            :: "r"(_m), "r"(_p) : "memory");                                           \
    } } while (0)
#define FENCE_ASYNC() asm volatile("fence.proxy.async.shared::cta;" ::: "memory")

__device__ __forceinline__ void ldmx4(uint32_t* r, uint32_t addr) {
    asm volatile("ldmatrix.sync.aligned.m8n8.x4.shared.b16 {%0,%1,%2,%3}, [%4];"
                 : "=r"(r[0]), "=r"(r[1]), "=r"(r[2]), "=r"(r[3]) : "r"(addr));
}
__device__ __forceinline__ void mma16816(float* d, const uint32_t* a, const uint32_t* b) {
    asm volatile(
        "mma.sync.aligned.m16n8k16.row.col.f32.bf16.bf16.f32 "
        "{%0,%1,%2,%3}, {%4,%5,%6,%7}, {%8,%9}, {%0,%1,%2,%3};"
        : "+f"(d[0]), "+f"(d[1]), "+f"(d[2]), "+f"(d[3])
        : "r"(a[0]), "r"(a[1]), "r"(a[2]), "r"(a[3]), "r"(b[0]), "r"(b[1]));
}

// ---------------- small kernels ----------------
__global__ void zero_kernel(float* p, size_t n) {
    size_t i = (size_t)blockIdx.x * blockDim.x + threadIdx.x;
    size_t s = (size_t)gridDim.x * blockDim.x;
    for (; i < n; i += s) p[i] = 0.f;
}

template <int C>
__global__ void gn_stats(const float* __restrict__ x, int n, float* __restrict__ part) {
    const int CG = C / 4;
    const int RPB = 256 / CG;
    int tid = threadIdx.x;
    int cg = tid % CG;
    int rsub = tid / CG;
    float4 s = {0, 0, 0, 0}, q = {0, 0, 0, 0};
    for (long r = (long)blockIdx.x * RPB + rsub; r < n; r += (long)gridDim.x * RPB) {
        float4 v = *(const float4*)(x + r * C + cg * 4);
        s.x += v.x; s.y += v.y; s.z += v.z; s.w += v.w;
        q.x += v.x * v.x; q.y += v.y * v.y; q.z += v.z * v.z; q.w += v.w * v.w;
    }
    __shared__ float4 sh[256], sq[256];
    sh[tid] = s; sq[tid] = q;
    __syncthreads();
    if (rsub == 0) {
        for (int j = 1; j < RPB; j++) {
            float4 t = sh[j * CG + cg];
            s.x += t.x; s.y += t.y; s.z += t.z; s.w += t.w;
            t = sq[j * CG + cg];
            q.x += t.x; q.y += t.y; q.z += t.z; q.w += t.w;
        }
        *(float4*)&part[blockIdx.x * C + cg * 4] = s;
        *(float4*)&part[NB * C + blockIdx.x * C + cg * 4] = q;
    }
}

template <int C, int CPG>
__global__ void gn_finalize(const float* __restrict__ part, const float* __restrict__ w,
                            const float* __restrict__ b, float rcount) {
    int c = threadIdx.x;
    float s = 0.f, q = 0.f;
    for (int blk = 0; blk < NB; blk++) {
        s += part[blk * C + c];
        q += part[NB * C + blk * C + c];
    }
    __shared__ float cs[256], cq[256];
    cs[c] = s; cq[c] = q;
    __syncthreads();
    __shared__ float mu[32], rs[32];
    if (c < C / CPG) {
        float S = 0.f, Q = 0.f;
        for (int j = 0; j < CPG; j++) { S += cs[c * CPG + j]; Q += cq[c * CPG + j]; }
        float m = S * rcount;
        float v = Q * rcount - m * m;
        mu[c] = m;
        rs[c] = rsqrtf(v + 1e-5f);
    }
    __syncthreads();
    int g = c / CPG;
    float sc = w[c] * rs[g];
    g_scale[c] = sc;
    g_shift[c] = b[c] - mu[g] * sc;
}

__global__ void downsample_kernel(const float* __restrict__ feats,
                                  const int* __restrict__ seg, int n) {
    long t = (long)blockIdx.x * blockDim.x + threadIdx.x;
    if (t >= (long)n * 32) return;
    int row = (int)(t >> 5);
    int q = (int)(t & 31);
    int c = q * 4;
    int s = seg[row];
    float4 f = *(const float4*)(feats + (long)row * 128 + c);
    float4 sc = *(const float4*)(g_scale + c);
    float4 sh = *(const float4*)(g_shift + c);
    float h0 = silu_f(f.x * sc.x + sh.x);
    float h1 = silu_f(f.y * sc.y + sh.y);
    float h2 = silu_f(f.z * sc.z + sh.z);
    float h3 = silu_f(f.w * sc.w + sh.w);
    float* hp = g_A + (long)s * 128 + c;
    float* xp = g_B + (long)s * 128 + c;
    atomicAdd(hp + 0, h0); atomicAdd(hp + 1, h1);
    atomicAdd(hp + 2, h2); atomicAdd(hp + 3, h3);
    atomicAdd(xp + 0, f.x); atomicAdd(xp + 1, f.y);
    atomicAdd(xp + 2, f.z); atomicAdd(xp + 3, f.w);
    if (q == 0) atomicAdd(g_cnt + s, 1.f);
}

__device__ __forceinline__ void split_store(bf16* ph, bf16* pl, size_t idx, float v) {
    bf16 h = __float2bfloat16(v);
    ph[idx] = h;
    pl[idx] = __float2bfloat16(v - __bfloat162float(h));
}

__global__ void finalize_down(int M) {
    long t = (long)blockIdx.x * blockDim.x + threadIdx.x;
    if (t >= (long)M * 32) return;
    int row = (int)(t >> 5);
    int c = (int)(t & 31) * 4;
    float ic = 1.f / fmaxf(g_cnt[row], 1.f);
    size_t base = (size_t)row * 128 + c;
    float4 va = *(const float4*)(g_A + base);
    float4 vb = *(const float4*)(g_B + base);
    split_store(g_hdh, g_hdl, base + 0, va.x * ic);
    split_store(g_hdh, g_hdl, base + 1, va.y * ic);
    split_store(g_hdh, g_hdl, base + 2, va.z * ic);
    split_store(g_hdh, g_hdl, base + 3, va.w * ic);
    split_store(g_xdh, g_xdl, base + 0, vb.x * ic);
    split_store(g_xdh, g_xdl, base + 1, vb.y * ic);
    split_store(g_xdh, g_xdl, base + 2, vb.z * ic);
    split_store(g_xdh, g_xdl, base + 3, vb.w * ic);
}

__global__ void apply_gn2(int M) {
    long t = (long)blockIdx.x * blockDim.x + threadIdx.x;
    if (t >= (long)M * 64) return;
    int row = (int)(t >> 6);
    int c = (int)(t & 63) * 4;
    size_t base = (size_t)row * 256 + c;
    float4 v = *(const float4*)(g_C + base);
    float4 sc = *(const float4*)(g_scale + c);
    float4 sh = *(const float4*)(g_shift + c);
    split_store(g_h2h, g_h2l, base + 0, silu_f(v.x * sc.x + sh.x));
    split_store(g_h2h, g_h2l, base + 1, silu_f(v.y * sc.y + sh.y));
    split_store(g_h2h, g_h2l, base + 2, silu_f(v.z * sc.z + sh.z));
    split_store(g_h2h, g_h2l, base + 3, silu_f(v.w * sc.w + sh.w));
}

// transpose + split + CHUNK/SWIZZLE: out elt = [(k*NCH+ch)*256 + n]*32 + (q^((n>>1)&3))*8 + o
// where ch=c>>5, q=(c>>3)&3, o=c&7.  Each [chunk][n] row of 32 elts = 64B, chunk = 16KB.
template <int CIN>
__global__ void prep_w(const float* __restrict__ W, bf16* __restrict__ wh,
                       bf16* __restrict__ wl, int total) {
    int idx = blockIdx.x * blockDim.x + threadIdx.x;
    int stride = gridDim.x * blockDim.x;
    const int NCH = CIN / 32;
    for (; idx < total; idx += stride) {
        int c = idx % CIN;
        int n = (idx / CIN) % 256;
        int k = idx / (CIN * 256);
        float v = W[((size_t)k * CIN + c) * 256 + n];
        bf16 h = __float2bfloat16(v);
        int ch = c >> 5, q = (c >> 3) & 3, o = c & 7;
        size_t dst = ((size_t)(k * NCH + ch) * 256 + n) * 32 + ((q ^ ((n >> 1) & 3)) << 3) + o;
        wh[dst] = h;
        wl[dst] = __float2bfloat16(v - __bfloat162float(h));
    }
}

// ---------------- HMMA gather-conv: bulk-copy B + cp.async A, pipelined ---------
// CTA 256 thr / 8 warps; tile 64(M) x 256(N); warp grid 2x4 -> 32x64 per warp.
// Chunks (tap, k0=32): A 64x32 hi+lo via cp.async (512 ops, zero-fill for missing
// rows); B 256x32 hi+lo via TWO cp.async.bulk copies of pre-swizzled 16KB blocks,
// completing on a per-stage mbarrier (expect_tx 32KB, parity=(i/3)&1).
// SMEM: A bufs 3x8KB @0, B bufs 3x32KB @24576, mbars @122880, nid @122912.
static constexpr int CONV_SMEM = 122912 + 28 * 64 * 4;

template <int CIN, bool FUSE_SKIP>
__global__ __launch_bounds__(256, 1) void conv_hmma(
    const bf16* __restrict__ xh, const bf16* __restrict__ xl,
    const bf16* __restrict__ wh, const bf16* __restrict__ wl,
    const bf16* __restrict__ sxh, const bf16* __restrict__ sxl,
    const bf16* __restrict__ swh, const bf16* __restrict__ swl,
    const float* __restrict__ bias, const float* __restrict__ bias2,
    const int* __restrict__ nbr, float* __restrict__ out, int M) {
    extern __shared__ char smem[];
    constexpr int NCH = CIN / 32;
    constexpr int NREG = 27 * NCH;
    constexpr int TC = NREG + (FUSE_SKIP ? 4 : 0);
    constexpr int NT = FUSE_SKIP ? 28 : 27;
    const uint32_t sbase = smem_u32(smem);
    const uint32_t mbars = sbase + 122880;
    int* nid = (int*)(smem + 122912);
    const int tid = threadIdx.x;
    const int mbase = blockIdx.x * 64;
    const int lane = tid & 31;
    const int wm = (tid >> 5) >> 2;   // 0..1
    const int wn = (tid >> 5) & 3;    // 0..3

    if (tid == 0) {
        MBARRIER_INIT(mbars + 0, 1);
        MBARRIER_INIT(mbars + 8, 1);
        MBARRIER_INIT(mbars + 16, 1);
    }
    // prefetch neighbor ids for all taps
    for (int u = tid; u < NT * 64; u += 256) {
        int tap = u >> 6;
        int r = mbase + (u & 63);
        nid[u] = (tap == 27) ? ((r < M) ? r : -1)
                             : ((r < M) ? nbr[(size_t)r * 27 + tap] : -1);
    }
    __syncthreads();

    float d[2][8][4];
#pragma unroll
    for (int a = 0; a < 2; a++)
#pragma unroll
        for (int b = 0; b < 8; b++)
#pragma unroll
            for (int c = 0; c < 4; c++) d[a][b][c] = 0.f;

    // issue chunk i: A via cp.async group; B via 2 bulk copies on stage mbarrier
    auto issueC = [&](int i) {
        int tap, c0, cin, ch;
        const bf16 *axh, *axl, *bwh, *bwl;
        if (i < NREG) {
            tap = i / NCH; ch = i % NCH; c0 = ch * 32; cin = CIN;
            axh = xh; axl = xl;
            bwh = wh + (size_t)(tap * NCH + ch) * 8192;
            bwl = wl + (size_t)(tap * NCH + ch) * 8192;
        } else {
            tap = 27; ch = i - NREG; c0 = ch * 32; cin = 128;
            axh = sxh; axl = sxl;
            bwh = swh + (size_t)ch * 8192;
            bwl = swl + (size_t)ch * 8192;
        }
        const int* nt = nid + tap * 64;
        const uint32_t ab = sbase + (i % 3) * 8192;
        const uint32_t bb = sbase + 24576 + (i % 3) * 32768;
        if (tid == 0) {
            FENCE_ASYNC();
            MBAR_ARRIVE_EXPECT(mbars + (i % 3) * 8, 32768u);
            cp_bulk_g2s(bb, bwh, 16384u, mbars + (i % 3) * 8);
            cp_bulk_g2s(bb + 16384, bwl, 16384u, mbars + (i % 3) * 8);
        }
#pragma unroll
        for (int w = 0; w < 2; w++) {
            int u = tid + w * 256;
            int plane = u >> 8, r = (u >> 2) & 63, q = u & 3;
            int src = nt[r];
            const bf16* sp = (src >= 0)
                ? ((plane ? axl : axh) + (size_t)src * cin + c0 + q * 8)
                : (const bf16*)g_zrow;
            cp_async16z(ab + plane * 4096 + r * 64 + ((q ^ ((r >> 1) & 3)) << 4),
                        sp, (src >= 0) ? 16u : 0u);
        }
        cp_commit();
    };

    issueC(0);
    if (TC > 1) issueC(1);
    if (TC > 2) issueC(2);

    for (int i = 0; i < TC; i++) {
        int ahead = TC - 1 - i;
        if (ahead >= 2) cp_wait2();
        else if (ahead == 1) cp_wait1();
        else cp_wait0();
        MBARRIER_WAIT_PARITY(mbars + (i % 3) * 8, (i / 3) & 1);
        __syncthreads();

        const uint32_t ab = sbase + (i % 3) * 8192;
        const uint32_t bb = sbase + 24576 + (i % 3) * 32768;
#pragma unroll
        for (int ks = 0; ks < 2; ks++) {
            uint32_t ah[2][4], al[2][4];
            const int u = ks * 2 + ((lane >> 4) & 1);
#pragma unroll
            for (int mt = 0; mt < 2; mt++) {
                int row = wm * 32 + mt * 16 + (lane & 15);
                uint32_t ad = ab + row * 64 + ((u ^ ((row >> 1) & 3)) << 4);
                ldmx4(ah[mt], ad);
                ldmx4(al[mt], ad + 4096);
            }
            const int brow = (lane & 7) + ((lane & 16) ? 8 : 0);
            const int bu = ks * 2 + ((lane >> 3) & 1);
#pragma unroll
            for (int p = 0; p < 4; p++) {
                int n = wn * 64 + p * 16 + brow;
                uint32_t bd = bb + n * 64 + ((bu ^ ((n >> 1) & 3)) << 4);
                uint32_t bh[4], bl[4];
                ldmx4(bh, bd);
                ldmx4(bl, bd + 16384);
#pragma unroll
                for (int mt = 0; mt < 2; mt++) {
                    mma16816(d[mt][2 * p + 0], ah[mt], &bh[0]);
                    mma16816(d[mt][2 * p + 1], ah[mt], &bh[2]);
                    mma16816(d[mt][2 * p + 0], ah[mt], &bl[0]);
                    mma16816(d[mt][2 * p + 1], ah[mt], &bl[2]);
                    mma16816(d[mt][2 * p + 0], al[mt], &bh[0]);
                    mma16816(d[mt][2 * p + 1], al[mt], &bh[2]);
                }
            }
        }
        __syncthreads();
        if (i + 3 < TC) issueC(i + 3);
    }

    // epilogue: direct global stores
#pragma unroll
    for (int mt = 0; mt < 2; mt++) {
        int r0 = mbase + wm * 32 + mt * 16 + lane / 4;
#pragma unroll
        for (int t = 0; t < 8; t++) {
            int gc = wn * 64 + t * 8 + (lane % 4) * 2;
            float bx = bias[gc], by = bias[gc + 1];
            if (FUSE_SKIP) { bx += bias2[gc]; by += bias2[gc + 1]; }
            if (r0 < M) {
                float2 v = {d[mt][t][0] + bx, d[mt][t][1] + by};
                *(float2*)(out + (size_t)r0 * 256 + gc) = v;
            }
            if (r0 + 8 < M) {
                float2 v = {d[mt][t][2] + bx, d[mt][t][3] + by};
                *(float2*)(out + (size_t)(r0 + 8) * 256 + gc) = v;
            }
        }
    }
}

// ---------------- launch ----------------
extern "C" void kernel_launch(void* const* d_in, const int* in_sizes, int n_in,
                              void* d_out, int out_size) {
    const float* feats = (const float*)d_in[0];
    const float* gn1_w = (const float*)d_in[1];
    const float* gn1_b = (const float*)d_in[2];
    const float* W1    = (const float*)d_in[3];
    const float* b1    = (const float*)d_in[4];
    const float* gn2_w = (const float*)d_in[5];
    const float* gn2_b = (const float*)d_in[6];
    const float* W2    = (const float*)d_in[7];
    const float* b2    = (const float*)d_in[8];
    const float* Wskip = (const float*)d_in[9];
    const float* bskip = (const float*)d_in[10];
    const int* pool_seg = (const int*)d_in[11];
    const int* nbr_idx  = (const int*)d_in[12];
    float* out = (float*)d_out;

    int N = in_sizes[0] / 128;
    int M = in_sizes[12] / 27;

    float *A, *B, *C, *cnt, *part;
    cudaGetSymbolAddress((void**)&A, g_A);
    cudaGetSymbolAddress((void**)&B, g_B);
    cudaGetSymbolAddress((void**)&C, g_C);
    cudaGetSymbolAddress((void**)&cnt, g_cnt);
    cudaGetSymbolAddress((void**)&part, g_part);
    bf16 *hdh, *hdl, *xdh, *xdl, *h2h, *h2l, *W1h, *W1l, *W2h, *W2l, *WSh, *WSl;
    cudaGetSymbolAddress((void**)&hdh, g_hdh);
    cudaGetSymbolAddress((void**)&hdl, g_hdl);
    cudaGetSymbolAddress((void**)&xdh, g_xdh);
    cudaGetSymbolAddress((void**)&xdl, g_xdl);
    cudaGetSymbolAddress((void**)&h2h, g_h2h);
    cudaGetSymbolAddress((void**)&h2l, g_h2l);
    cudaGetSymbolAddress((void**)&W1h, g_W1h);
    cudaGetSymbolAddress((void**)&W1l, g_W1l);
    cudaGetSymbolAddress((void**)&W2h, g_W2h);
    cudaGetSymbolAddress((void**)&W2l, g_W2l);
    cudaGetSymbolAddress((void**)&WSh, g_WSh);
    cudaGetSymbolAddress((void**)&WSl, g_WSl);

    cudaFuncSetAttribute(conv_hmma<128, false>,
                         cudaFuncAttributeMaxDynamicSharedMemorySize, CONV_SMEM);
    cudaFuncSetAttribute(conv_hmma<256, true>,
                         cudaFuncAttributeMaxDynamicSharedMemorySize, CONV_SMEM);

    // zero atomic accumulators (graph replays -> re-zero every launch)
    zero_kernel<<<4096, 256>>>(A, (size_t)M * 128);
    zero_kernel<<<4096, 256>>>(B, (size_t)M * 128);
    zero_kernel<<<256, 256>>>(cnt, (size_t)M);

    // weight transpose + bf16 hi/lo split + chunked/pre-swizzled layout
    prep_w<128><<<1024, 256>>>(W1, W1h, W1l, 27 * 256 * 128);
    prep_w<256><<<2048, 256>>>(W2, W2h, W2l, 27 * 256 * 256);
    prep_w<128><<<128, 256>>>(Wskip, WSh, WSl, 256 * 128);

    // GN1 stats + finalize
    gn_stats<128><<<NB, 256>>>(feats, N, part);
    gn_finalize<128, 4><<<1, 128>>>(part, gn1_w, gn1_b, 1.f / ((float)N * 4.f));

    // GN1 apply + SiLU + segment sums; then means + hi/lo planes
    long dthreads = (long)N * 32;
    downsample_kernel<<<(int)((dthreads + 255) / 256), 256>>>(feats, pool_seg, N);
    long fthreads = (long)M * 32;
    finalize_down<<<(int)((fthreads + 255) / 256), 256>>>(M);

    int nconv = (M + 63) / 64;

    // conv1: h1 = conv(h_d, W1) + b1
    conv_hmma<128, false><<<nconv, 256, CONV_SMEM>>>(
        hdh, hdl, W1h, W1l, nullptr, nullptr, nullptr, nullptr,
        b1, nullptr, nbr_idx, C, M);

    // GN2 stats + finalize + apply (emits h2 hi/lo planes)
    gn_stats<256><<<NB, 256>>>(C, M, part);
    gn_finalize<256, 8><<<1, 256>>>(part, gn2_w, gn2_b, 1.f / ((float)M * 8.f));
    long athreads = (long)M * 64;
    apply_gn2<<<(int)((athreads + 255) / 256), 256>>>(M);

    // conv2 + fused skip: out = conv(h2, W2) + b2 + x_d @ Wskip + bskip
    conv_hmma<256, true><<<nconv, 256, CONV_SMEM>>>(
        h2h, h2l, W2h, W2l, xdh, xdl, WSh, WSl,
        b2, bskip, nbr_idx, out, M);
}

// round 8
// speedup vs baseline: 6.0610x; 1.1768x over previous
#include <cuda_runtime.h>
#include <cuda_bf16.h>
#include <cstdint>

#define MMAX 200704
#define NB 256

typedef __nv_bfloat16 bf16;

// ---------------- scratch (device globals; no allocation allowed) ----------------
__device__ float g_A[(size_t)MMAX * 128];   // h segment-sum accumulator
__device__ float g_B[(size_t)MMAX * 128];   // x segment-sum accumulator
__device__ float g_C[(size_t)MMAX * 256];   // h1 (conv1 out, fp32 for GN2 stats)
__device__ float g_cnt[MMAX];
__device__ float g_part[2 * NB * 256];
__device__ float g_scale[256];
__device__ float g_shift[256];
__device__ __align__(16) bf16 g_zrow[64];   // safe src for zero-fill cp.async
// bf16 hi/lo operand planes
__device__ bf16 g_hdh[(size_t)MMAX * 128];
__device__ bf16 g_hdl[(size_t)MMAX * 128];
__device__ bf16 g_xdh[(size_t)MMAX * 128];
__device__ bf16 g_xdl[(size_t)MMAX * 128];
__device__ bf16 g_h2h[(size_t)MMAX * 256];
__device__ bf16 g_h2l[(size_t)MMAX * 256];
// weights: chunked+pre-swizzled layout [tap*NCH+ch][n=256][32] (16KB blocks)
__device__ __align__(16) bf16 g_W1h[27 * 256 * 128];
__device__ __align__(16) bf16 g_W1l[27 * 256 * 128];
__device__ __align__(16) bf16 g_W2h[27 * 256 * 256];
__device__ __align__(16) bf16 g_W2l[27 * 256 * 256];
__device__ __align__(16) bf16 g_WSh[256 * 128];
__device__ __align__(16) bf16 g_WSl[256 * 128];

__device__ __forceinline__ float silu_f(float x) { return x / (1.f + __expf(-x)); }

__device__ __forceinline__ uint32_t smem_u32(const void* p) {
    uint32_t a;
    asm("{ .reg .u64 t; cvta.to.shared.u64 t, %1; cvt.u32.u64 %0, t; }" : "=r"(a) : "l"(p));
    return a;
}
// zero-fill form: src-size=0 -> writes 16 zero bytes, NO global read issued
__device__ __forceinline__ void cp_async16z(uint32_t dst, const void* src, uint32_t srcsz) {
    asm volatile("cp.async.cg.shared.global [%0], [%1], 16, %2;"
                 :: "r"(dst), "l"(src), "r"(srcsz));
}
__device__ __forceinline__ void cp_commit() {
    asm volatile("cp.async.commit_group;" ::: "memory");
}
__device__ __forceinline__ void cp_wait0() { asm volatile("cp.async.wait_group 0;" ::: "memory"); }
__device__ __forceinline__ void cp_wait1() { asm volatile("cp.async.wait_group 1;" ::: "memory"); }
__device__ __forceinline__ void cp_wait2() { asm volatile("cp.async.wait_group 2;" ::: "memory"); }
// bulk g2s copy completing on an mbarrier (sm_90 base feature)
__device__ __forceinline__ void cp_bulk_g2s(uint32_t dst, const void* src, uint32_t bytes,
                                            uint32_t mbar) {
    asm volatile(
        "cp.async.bulk.shared::cta.global.mbarrier::complete_tx::bytes [%0], [%1], %2, [%3];"
        :: "r"(dst), "l"(src), "r"(bytes), "r"(mbar) : "memory");
}
#define MBARRIER_INIT(addr, cnt) \
    asm volatile("mbarrier.init.shared.b64 [%0], %1;" :: "r"(addr), "r"(cnt) : "memory")
#define MBAR_ARRIVE_EXPECT(m, b) \
    asm volatile("mbarrier.arrive.expect_tx.shared.b64 _, [%0], %1;" :: "r"(m), "r"(b) : "memory")
#define MBARRIER_WAIT_PARITY(addr, par) do {                                           \
    uint32_t _m = (addr); uint32_t _p = (par); uint32_t _done;                         \
    asm volatile("{\n\t.reg .pred p;\n\t"                                              \
        "mbarrier.try_wait.parity.acquire.cta.shared::cta.b64 p, [%1], %2;\n\t"        \
        "selp.b32 %0, 1, 0, p;\n\t}" : "=r"(_done) : "r"(_m), "r"(_p) : "memory");     \
    if (!_done) {                                                                      \
        asm volatile("{\n\t.reg .pred P1;\n\tWL_%=:\n\t"                               \
            "mbarrier.try_wait.parity.acquire.cta.shared::cta.b64 P1, [%0], %1, 0x989680;\n\t" \
            "@P1 bra.uni WD_%=;\n\tbra.uni WL_%=;\n\tWD_%=:\n\t}"                      \
            :: "r"(_m), "r"(_p) : "memory");                                           \
    } } while (0)
#define FENCE_ASYNC() asm volatile("fence.proxy.async.shared::cta;" ::: "memory")

__device__ __forceinline__ void ldmx4(uint32_t* r, uint32_t addr) {
    asm volatile("ldmatrix.sync.aligned.m8n8.x4.shared.b16 {%0,%1,%2,%3}, [%4];"
                 : "=r"(r[0]), "=r"(r[1]), "=r"(r[2]), "=r"(r[3]) : "r"(addr));
}
__device__ __forceinline__ void mma16816(float* d, const uint32_t* a, const uint32_t* b) {
    asm volatile(
        "mma.sync.aligned.m16n8k16.row.col.f32.bf16.bf16.f32 "
        "{%0,%1,%2,%3}, {%4,%5,%6,%7}, {%8,%9}, {%0,%1,%2,%3};"
        : "+f"(d[0]), "+f"(d[1]), "+f"(d[2]), "+f"(d[3])
        : "r"(a[0]), "r"(a[1]), "r"(a[2]), "r"(a[3]), "r"(b[0]), "r"(b[1]));
}

// ---------------- small kernels ----------------
__global__ void zero_kernel(float* p, size_t n) {
    size_t i = (size_t)blockIdx.x * blockDim.x + threadIdx.x;
    size_t s = (size_t)gridDim.x * blockDim.x;
    for (; i < n; i += s) p[i] = 0.f;
}

template <int C>
__global__ void gn_stats(const float* __restrict__ x, int n, float* __restrict__ part) {
    const int CG = C / 4;
    const int RPB = 256 / CG;
    int tid = threadIdx.x;
    int cg = tid % CG;
    int rsub = tid / CG;
    float4 s = {0, 0, 0, 0}, q = {0, 0, 0, 0};
    for (long r = (long)blockIdx.x * RPB + rsub; r < n; r += (long)gridDim.x * RPB) {
        float4 v = *(const float4*)(x + r * C + cg * 4);
        s.x += v.x; s.y += v.y; s.z += v.z; s.w += v.w;
        q.x += v.x * v.x; q.y += v.y * v.y; q.z += v.z * v.z; q.w += v.w * v.w;
    }
    __shared__ float4 sh[256], sq[256];
    sh[tid] = s; sq[tid] = q;
    __syncthreads();
    if (rsub == 0) {
        for (int j = 1; j < RPB; j++) {
            float4 t = sh[j * CG + cg];
            s.x += t.x; s.y += t.y; s.z += t.z; s.w += t.w;
            t = sq[j * CG + cg];
            q.x += t.x; q.y += t.y; q.z += t.z; q.w += t.w;
        }
        *(float4*)&part[blockIdx.x * C + cg * 4] = s;
        *(float4*)&part[NB * C + blockIdx.x * C + cg * 4] = q;
    }
}

template <int C, int CPG>
__global__ void gn_finalize(const float* __restrict__ part, const float* __restrict__ w,
                            const float* __restrict__ b, float rcount) {
    int c = threadIdx.x;
    float s = 0.f, q = 0.f;
    for (int blk = 0; blk < NB; blk++) {
        s += part[blk * C + c];
        q += part[NB * C + blk * C + c];
    }
    __shared__ float cs[256], cq[256];
    cs[c] = s; cq[c] = q;
    __syncthreads();
    __shared__ float mu[32], rs[32];
    if (c < C / CPG) {
        float S = 0.f, Q = 0.f;
        for (int j = 0; j < CPG; j++) { S += cs[c * CPG + j]; Q += cq[c * CPG + j]; }
        float m = S * rcount;
        float v = Q * rcount - m * m;
        mu[c] = m;
        rs[c] = rsqrtf(v + 1e-5f);
    }
    __syncthreads();
    int g = c / CPG;
    float sc = w[c] * rs[g];
    g_scale[c] = sc;
    g_shift[c] = b[c] - mu[g] * sc;
}

__global__ void downsample_kernel(const float* __restrict__ feats,
                                  const int* __restrict__ seg, int n) {
    long t = (long)blockIdx.x * blockDim.x + threadIdx.x;
    if (t >= (long)n * 32) return;
    int row = (int)(t >> 5);
    int q = (int)(t & 31);
    int c = q * 4;
    int s = seg[row];
    float4 f = *(const float4*)(feats + (long)row * 128 + c);
    float4 sc = *(const float4*)(g_scale + c);
    float4 sh = *(const float4*)(g_shift + c);
    float h0 = silu_f(f.x * sc.x + sh.x);
    float h1 = silu_f(f.y * sc.y + sh.y);
    float h2 = silu_f(f.z * sc.z + sh.z);
    float h3 = silu_f(f.w * sc.w + sh.w);
    float* hp = g_A + (long)s * 128 + c;
    float* xp = g_B + (long)s * 128 + c;
    atomicAdd(hp + 0, h0); atomicAdd(hp + 1, h1);
    atomicAdd(hp + 2, h2); atomicAdd(hp + 3, h3);
    atomicAdd(xp + 0, f.x); atomicAdd(xp + 1, f.y);
    atomicAdd(xp + 2, f.z); atomicAdd(xp + 3, f.w);
    if (q == 0) atomicAdd(g_cnt + s, 1.f);
}

__device__ __forceinline__ void split_store(bf16* ph, bf16* pl, size_t idx, float v) {
    bf16 h = __float2bfloat16(v);
    ph[idx] = h;
    pl[idx] = __float2bfloat16(v - __bfloat162float(h));
}

__global__ void finalize_down(int M) {
    long t = (long)blockIdx.x * blockDim.x + threadIdx.x;
    if (t >= (long)M * 32) return;
    int row = (int)(t >> 5);
    int c = (int)(t & 31) * 4;
    float ic = 1.f / fmaxf(g_cnt[row], 1.f);
    size_t base = (size_t)row * 128 + c;
    float4 va = *(const float4*)(g_A + base);
    float4 vb = *(const float4*)(g_B + base);
    split_store(g_hdh, g_hdl, base + 0, va.x * ic);
    split_store(g_hdh, g_hdl, base + 1, va.y * ic);
    split_store(g_hdh, g_hdl, base + 2, va.z * ic);
    split_store(g_hdh, g_hdl, base + 3, va.w * ic);
    split_store(g_xdh, g_xdl, base + 0, vb.x * ic);
    split_store(g_xdh, g_xdl, base + 1, vb.y * ic);
    split_store(g_xdh, g_xdl, base + 2, vb.z * ic);
    split_store(g_xdh, g_xdl, base + 3, vb.w * ic);
}

__global__ void apply_gn2(int M) {
    long t = (long)blockIdx.x * blockDim.x + threadIdx.x;
    if (t >= (long)M * 64) return;
    int row = (int)(t >> 6);
    int c = (int)(t & 63) * 4;
    size_t base = (size_t)row * 256 + c;
    float4 v = *(const float4*)(g_C + base);
    float4 sc = *(const float4*)(g_scale + c);
    float4 sh = *(const float4*)(g_shift + c);
    split_store(g_h2h, g_h2l, base + 0, silu_f(v.x * sc.x + sh.x));
    split_store(g_h2h, g_h2l, base + 1, silu_f(v.y * sc.y + sh.y));
    split_store(g_h2h, g_h2l, base + 2, silu_f(v.z * sc.z + sh.z));
    split_store(g_h2h, g_h2l, base + 3, silu_f(v.w * sc.w + sh.w));
}

// transpose + split + CHUNK/SWIZZLE: out elt = [(k*NCH+ch)*256 + n]*32 + (q^((n>>1)&3))*8 + o
template <int CIN>
__global__ void prep_w(const float* __restrict__ W, bf16* __restrict__ wh,
                       bf16* __restrict__ wl, int total) {
    int idx = blockIdx.x * blockDim.x + threadIdx.x;
    int stride = gridDim.x * blockDim.x;
    const int NCH = CIN / 32;
    for (; idx < total; idx += stride) {
        int c = idx % CIN;
        int n = (idx / CIN) % 256;
        int k = idx / (CIN * 256);
        float v = W[((size_t)k * CIN + c) * 256 + n];
        bf16 h = __float2bfloat16(v);
        int ch = c >> 5, q = (c >> 3) & 3, o = c & 7;
        size_t dst = ((size_t)(k * NCH + ch) * 256 + n) * 32 + ((q ^ ((n >> 1) & 3)) << 3) + o;
        wh[dst] = h;
        wl[dst] = __float2bfloat16(v - __bfloat162float(h));
    }
}

// ---------------- HMMA gather-conv: N-split, 2 CTAs/SM, 4-stage pipeline --------
// Grid = (M/64 tiles) x 2 N-halves. CTA 256 thr / 8 warps; tile 64(M) x 128(N);
// warp grid 2x4 -> 32x32 per warp (32 accums -> ~110 regs, fits 128-cap for occ 2).
// Chunks (tap, k0=32): A 64x32 hi+lo cp.async (zero-fill); B 128x32 hi+lo via
// 2 bulk copies of pre-swizzled blocks (swizzle invariant under n+=128).
// 4 stages, issue(i+3) BEFORE compute(i) -> ONE __syncthreads per chunk.
// SMEM: A 4x8KB @0, B 4x16KB @32768, mbars @98304, nid @98336.
static constexpr int CONV_SMEM = 98336 + 28 * 64 * 4;

template <int CIN, bool FUSE_SKIP>
__global__ __launch_bounds__(256, 2) void conv_hmma(
    const bf16* __restrict__ xh, const bf16* __restrict__ xl,
    const bf16* __restrict__ wh, const bf16* __restrict__ wl,
    const bf16* __restrict__ sxh, const bf16* __restrict__ sxl,
    const bf16* __restrict__ swh, const bf16* __restrict__ swl,
    const float* __restrict__ bias, const float* __restrict__ bias2,
    const int* __restrict__ nbr, float* __restrict__ out, int M) {
    extern __shared__ char smem[];
    constexpr int NCH = CIN / 32;
    constexpr int NREG = 27 * NCH;
    constexpr int TC = NREG + (FUSE_SKIP ? 4 : 0);
    constexpr int NT = FUSE_SKIP ? 28 : 27;
    const uint32_t sbase = smem_u32(smem);
    const uint32_t mbars = sbase + 98304;
    int* nid = (int*)(smem + 98336);
    const int tid = threadIdx.x;
    const int mbase = (blockIdx.x >> 1) * 64;
    const int n0 = (blockIdx.x & 1) * 128;
    const int lane = tid & 31;
    const int wm = (tid >> 5) >> 2;   // 0..1
    const int wn = (tid >> 5) & 3;    // 0..3

    if (tid == 0) {
        MBARRIER_INIT(mbars + 0, 1);
        MBARRIER_INIT(mbars + 8, 1);
        MBARRIER_INIT(mbars + 16, 1);
        MBARRIER_INIT(mbars + 24, 1);
    }
    for (int u = tid; u < NT * 64; u += 256) {
        int tap = u >> 6;
        int r = mbase + (u & 63);
        nid[u] = (tap == 27) ? ((r < M) ? r : -1)
                             : ((r < M) ? nbr[(size_t)r * 27 + tap] : -1);
    }
    __syncthreads();

    float d[2][4][4];
#pragma unroll
    for (int a = 0; a < 2; a++)
#pragma unroll
        for (int b = 0; b < 4; b++)
#pragma unroll
            for (int c = 0; c < 4; c++) d[a][b][c] = 0.f;

    // issue chunk i: A via cp.async group; B-half via 2 bulk copies (8KB each)
    auto issueC = [&](int i) {
        int tap, c0, cin, ch;
        const bf16 *axh, *axl, *bwh, *bwl;
        if (i < NREG) {
            tap = i / NCH; ch = i % NCH; c0 = ch * 32; cin = CIN;
            axh = xh; axl = xl;
            bwh = wh + (size_t)(tap * NCH + ch) * 8192 + n0 * 32;
            bwl = wl + (size_t)(tap * NCH + ch) * 8192 + n0 * 32;
        } else {
            tap = 27; ch = i - NREG; c0 = ch * 32; cin = 128;
            axh = sxh; axl = sxl;
            bwh = swh + (size_t)ch * 8192 + n0 * 32;
            bwl = swl + (size_t)ch * 8192 + n0 * 32;
        }
        const int* nt = nid + tap * 64;
        const uint32_t ab = sbase + (i & 3) * 8192;
        const uint32_t bb = sbase + 32768 + (i & 3) * 16384;
        if (tid == 0) {
            FENCE_ASYNC();
            MBAR_ARRIVE_EXPECT(mbars + (i & 3) * 8, 16384u);
            cp_bulk_g2s(bb, bwh, 8192u, mbars + (i & 3) * 8);
            cp_bulk_g2s(bb + 8192, bwl, 8192u, mbars + (i & 3) * 8);
        }
#pragma unroll
        for (int w = 0; w < 2; w++) {
            int u = tid + w * 256;
            int plane = u >> 8, r = (u >> 2) & 63, q = u & 3;
            int src = nt[r];
            const bf16* sp = (src >= 0)
                ? ((plane ? axl : axh) + (size_t)src * cin + c0 + q * 8)
                : (const bf16*)g_zrow;
            cp_async16z(ab + plane * 4096 + r * 64 + ((q ^ ((r >> 1) & 3)) << 4),
                        sp, (src >= 0) ? 16u : 0u);
        }
        cp_commit();
    };

    issueC(0);
    if (TC > 1) issueC(1);
    if (TC > 2) issueC(2);

    for (int i = 0; i < TC; i++) {
        int newest = (TC - 1 < i + 2) ? (TC - 1) : (i + 2);
        int ahead = newest - i;
        if (ahead >= 2) cp_wait2();
        else if (ahead == 1) cp_wait1();
        else cp_wait0();
        MBARRIER_WAIT_PARITY(mbars + (i & 3) * 8, (i >> 2) & 1);
        __syncthreads();
        if (i + 3 < TC) issueC(i + 3);   // writes buf (i-1)&3: drained by sync

        const uint32_t ab = sbase + (i & 3) * 8192;
        const uint32_t bb = sbase + 32768 + (i & 3) * 16384;
#pragma unroll
        for (int ks = 0; ks < 2; ks++) {
            uint32_t ah[2][4], al[2][4];
            const int u = ks * 2 + ((lane >> 4) & 1);
#pragma unroll
            for (int mt = 0; mt < 2; mt++) {
                int row = wm * 32 + mt * 16 + (lane & 15);
                uint32_t ad = ab + row * 64 + ((u ^ ((row >> 1) & 3)) << 4);
                ldmx4(ah[mt], ad);
                ldmx4(al[mt], ad + 4096);
            }
            const int brow = (lane & 7) + ((lane & 16) ? 8 : 0);
            const int bu = ks * 2 + ((lane >> 3) & 1);
#pragma unroll
            for (int p = 0; p < 2; p++) {
                int nl = wn * 32 + p * 16 + brow;   // local col in [0,128)
                uint32_t bd = bb + nl * 64 + ((bu ^ ((nl >> 1) & 3)) << 4);
                uint32_t bh[4], bl[4];
                ldmx4(bh, bd);
                ldmx4(bl, bd + 8192);
#pragma unroll
                for (int mt = 0; mt < 2; mt++) {
                    mma16816(d[mt][2 * p + 0], ah[mt], &bh[0]);
                    mma16816(d[mt][2 * p + 1], ah[mt], &bh[2]);
                    mma16816(d[mt][2 * p + 0], ah[mt], &bl[0]);
                    mma16816(d[mt][2 * p + 1], ah[mt], &bl[2]);
                    mma16816(d[mt][2 * p + 0], al[mt], &bh[0]);
                    mma16816(d[mt][2 * p + 1], al[mt], &bh[2]);
                }
            }
        }
    }

    // epilogue: direct global stores
#pragma unroll
    for (int mt = 0; mt < 2; mt++) {
        int r0 = mbase + wm * 32 + mt * 16 + lane / 4;
#pragma unroll
        for (int t = 0; t < 4; t++) {
            int gc = n0 + wn * 32 + t * 8 + (lane % 4) * 2;
            float bx = bias[gc], by = bias[gc + 1];
            if (FUSE_SKIP) { bx += bias2[gc]; by += bias2[gc + 1]; }
            if (r0 < M) {
                float2 v = {d[mt][t][0] + bx, d[mt][t][1] + by};
                *(float2*)(out + (size_t)r0 * 256 + gc) = v;
            }
            if (r0 + 8 < M) {
                float2 v = {d[mt][t][2] + bx, d[mt][t][3] + by};
                *(float2*)(out + (size_t)(r0 + 8) * 256 + gc) = v;
            }
        }
    }
}

// ---------------- launch ----------------
extern "C" void kernel_launch(void* const* d_in, const int* in_sizes, int n_in,
                              void* d_out, int out_size) {
    const float* feats = (const float*)d_in[0];
    const float* gn1_w = (const float*)d_in[1];
    const float* gn1_b = (const float*)d_in[2];
    const float* W1    = (const float*)d_in[3];
    const float* b1    = (const float*)d_in[4];
    const float* gn2_w = (const float*)d_in[5];
    const float* gn2_b = (const float*)d_in[6];
    const float* W2    = (const float*)d_in[7];
    const float* b2    = (const float*)d_in[8];
    const float* Wskip = (const float*)d_in[9];
    const float* bskip = (const float*)d_in[10];
    const int* pool_seg = (const int*)d_in[11];
    const int* nbr_idx  = (const int*)d_in[12];
    float* out = (float*)d_out;

    int N = in_sizes[0] / 128;
    int M = in_sizes[12] / 27;

    float *A, *B, *C, *cnt, *part;
    cudaGetSymbolAddress((void**)&A, g_A);
    cudaGetSymbolAddress((void**)&B, g_B);
    cudaGetSymbolAddress((void**)&C, g_C);
    cudaGetSymbolAddress((void**)&cnt, g_cnt);
    cudaGetSymbolAddress((void**)&part, g_part);
    bf16 *hdh, *hdl, *xdh, *xdl, *h2h, *h2l, *W1h, *W1l, *W2h, *W2l, *WSh, *WSl;
    cudaGetSymbolAddress((void**)&hdh, g_hdh);
    cudaGetSymbolAddress((void**)&hdl, g_hdl);
    cudaGetSymbolAddress((void**)&xdh, g_xdh);
    cudaGetSymbolAddress((void**)&xdl, g_xdl);
    cudaGetSymbolAddress((void**)&h2h, g_h2h);
    cudaGetSymbolAddress((void**)&h2l, g_h2l);
    cudaGetSymbolAddress((void**)&W1h, g_W1h);
    cudaGetSymbolAddress((void**)&W1l, g_W1l);
    cudaGetSymbolAddress((void**)&W2h, g_W2h);
    cudaGetSymbolAddress((void**)&W2l, g_W2l);
    cudaGetSymbolAddress((void**)&WSh, g_WSh);
    cudaGetSymbolAddress((void**)&WSl, g_WSl);

    cudaFuncSetAttribute(conv_hmma<128, false>,
                         cudaFuncAttributeMaxDynamicSharedMemorySize, CONV_SMEM);
    cudaFuncSetAttribute(conv_hmma<256, true>,
                         cudaFuncAttributeMaxDynamicSharedMemorySize, CONV_SMEM);

    // zero atomic accumulators (graph replays -> re-zero every launch)
    zero_kernel<<<4096, 256>>>(A, (size_t)M * 128);
    zero_kernel<<<4096, 256>>>(B, (size_t)M * 128);
    zero_kernel<<<256, 256>>>(cnt, (size_t)M);

    // weight transpose + bf16 hi/lo split + chunked/pre-swizzled layout
    prep_w<128><<<1024, 256>>>(W1, W1h, W1l, 27 * 256 * 128);
    prep_w<256><<<2048, 256>>>(W2, W2h, W2l, 27 * 256 * 256);
    prep_w<128><<<128, 256>>>(Wskip, WSh, WSl, 256 * 128);

    // GN1 stats + finalize
    gn_stats<128><<<NB, 256>>>(feats, N, part);
    gn_finalize<128, 4><<<1, 128>>>(part, gn1_w, gn1_b, 1.f / ((float)N * 4.f));

    // GN1 apply + SiLU + segment sums; then means + hi/lo planes
    long dthreads = (long)N * 32;
    downsample_kernel<<<(int)((dthreads + 255) / 256), 256>>>(feats, pool_seg, N);
    long fthreads = (long)M * 32;
    finalize_down<<<(int)((fthreads + 255) / 256), 256>>>(M);

    int nconv = ((M + 63) / 64) * 2;   // x2 N-halves

    // conv1: h1 = conv(h_d, W1) + b1
    conv_hmma<128, false><<<nconv, 256, CONV_SMEM>>>(
        hdh, hdl, W1h, W1l, nullptr, nullptr, nullptr, nullptr,
        b1, nullptr, nbr_idx, C, M);

    // GN2 stats + finalize + apply (emits h2 hi/lo planes)
    gn_stats<256><<<NB, 256>>>(C, M, part);
    gn_finalize<256, 8><<<1, 256>>>(part, gn2_w, gn2_b, 1.f / ((float)M * 8.f));
    long athreads = (long)M * 64;
    apply_gn2<<<(int)((athreads + 255) / 256), 256>>>(M);

    // conv2 + fused skip: out = conv(h2, W2) + b2 + x_d @ Wskip + bskip
    conv_hmma<256, true><<<nconv, 256, CONV_SMEM>>>(
        h2h, h2l, W2h, W2l, xdh, xdl, WSh, WSl,
        b2, bskip, nbr_idx, out, M);
}

// round 9
// speedup vs baseline: 12.7121x; 2.0973x over previous
#include <cuda_runtime.h>
#include <cuda_bf16.h>
#include <cuda_fp16.h>
#include <cstdint>

#define MMAX 200704
#define NB 256

typedef __half fh;

// ---------------- scratch (device globals; no allocation allowed) ----------------
__device__ float g_A[(size_t)MMAX * 128];   // h segment-sum accumulator
__device__ float g_B[(size_t)MMAX * 128];   // x segment-sum accumulator
__device__ float g_C[(size_t)MMAX * 256];   // h1 (conv1 out, fp32 for GN2 stats)
__device__ float g_cnt[MMAX];
__device__ float g_part[2 * NB * 256];
__device__ float g_scale[256];
__device__ float g_shift[256];
__device__ __align__(16) fh g_zrow[64];     // safe src for zero-fill cp.async
// fp16 operand planes (single plane each)
__device__ fh g_hd[(size_t)MMAX * 128];
__device__ fh g_xd[(size_t)MMAX * 128];
__device__ fh g_h2[(size_t)MMAX * 256];
// weights: chunked+pre-swizzled layout [tap*NCH+ch][n=256][32] (fp16, 16KB blocks)
__device__ __align__(16) fh g_W1[27 * 256 * 128];
__device__ __align__(16) fh g_W2[27 * 256 * 256];
__device__ __align__(16) fh g_WS[256 * 128];

__device__ __forceinline__ float silu_f(float x) { return x / (1.f + __expf(-x)); }

__device__ __forceinline__ uint32_t smem_u32(const void* p) {
    uint32_t a;
    asm("{ .reg .u64 t; cvta.to.shared.u64 t, %1; cvt.u32.u64 %0, t; }" : "=r"(a) : "l"(p));
    return a;
}
// zero-fill form: src-size=0 -> writes 16 zero bytes, NO global read issued
__device__ __forceinline__ void cp_async16z(uint32_t dst, const void* src, uint32_t srcsz) {
    asm volatile("cp.async.cg.shared.global [%0], [%1], 16, %2;"
                 :: "r"(dst), "l"(src), "r"(srcsz));
}
__device__ __forceinline__ void cp_commit() {
    asm volatile("cp.async.commit_group;" ::: "memory");
}
__device__ __forceinline__ void cp_wait0() { asm volatile("cp.async.wait_group 0;" ::: "memory"); }
__device__ __forceinline__ void cp_wait1() { asm volatile("cp.async.wait_group 1;" ::: "memory"); }
__device__ __forceinline__ void cp_wait2() { asm volatile("cp.async.wait_group 2;" ::: "memory"); }
// bulk g2s copy completing on an mbarrier (sm_90 base feature)
__device__ __forceinline__ void cp_bulk_g2s(uint32_t dst, const void* src, uint32_t bytes,
                                            uint32_t mbar) {
    asm volatile(
        "cp.async.bulk.shared::cta.global.mbarrier::complete_tx::bytes [%0], [%1], %2, [%3];"
        :: "r"(dst), "l"(src), "r"(bytes), "r"(mbar) : "memory");
}
#define MBARRIER_INIT(addr, cnt) \
    asm volatile("mbarrier.init.shared.b64 [%0], %1;" :: "r"(addr), "r"(cnt) : "memory")
#define MBAR_ARRIVE_EXPECT(m, b) \
    asm volatile("mbarrier.arrive.expect_tx.shared.b64 _, [%0], %1;" :: "r"(m), "r"(b) : "memory")
#define MBARRIER_WAIT_PARITY(addr, par) do {                                           \
    uint32_t _m = (addr); uint32_t _p = (par); uint32_t _done;                         \
    asm volatile("{\n\t.reg .pred p;\n\t"                                              \
        "mbarrier.try_wait.parity.acquire.cta.shared::cta.b64 p, [%1], %2;\n\t"        \
        "selp.b32 %0, 1, 0, p;\n\t}" : "=r"(_done) : "r"(_m), "r"(_p) : "memory");     \
    if (!_done) {                                                                      \
        asm volatile("{\n\t.reg .pred P1;\n\tWL_%=:\n\t"                               \
            "mbarrier.try_wait.parity.acquire.cta.shared::cta.b64 P1, [%0], %1, 0x989680;\n\t" \
            "@P1 bra.uni WD_%=;\n\tbra.uni WL_%=;\n\tWD_%=:\n\t}"                      \
            :: "r"(_m), "r"(_p) : "memory");                                           \
    } } while (0)
#define FENCE_ASYNC() asm volatile("fence.proxy.async.shared::cta;" ::: "memory")

__device__ __forceinline__ void ldmx4(uint32_t* r, uint32_t addr) {
    asm volatile("ldmatrix.sync.aligned.m8n8.x4.shared.b16 {%0,%1,%2,%3}, [%4];"
                 : "=r"(r[0]), "=r"(r[1]), "=r"(r[2]), "=r"(r[3]) : "r"(addr));
}
__device__ __forceinline__ void mma16816(float* d, const uint32_t* a, const uint32_t* b) {
    asm volatile(
        "mma.sync.aligned.m16n8k16.row.col.f32.f16.f16.f32 "
        "{%0,%1,%2,%3}, {%4,%5,%6,%7}, {%8,%9}, {%0,%1,%2,%3};"
        : "+f"(d[0]), "+f"(d[1]), "+f"(d[2]), "+f"(d[3])
        : "r"(a[0]), "r"(a[1]), "r"(a[2]), "r"(a[3]), "r"(b[0]), "r"(b[1]));
}

// ---------------- small kernels ----------------
__global__ void zero_kernel(float* p, size_t n) {
    size_t i = (size_t)blockIdx.x * blockDim.x + threadIdx.x;
    size_t s = (size_t)gridDim.x * blockDim.x;
    for (; i < n; i += s) p[i] = 0.f;
}

template <int C>
__global__ void gn_stats(const float* __restrict__ x, int n, float* __restrict__ part) {
    const int CG = C / 4;
    const int RPB = 256 / CG;
    int tid = threadIdx.x;
    int cg = tid % CG;
    int rsub = tid / CG;
    float4 s = {0, 0, 0, 0}, q = {0, 0, 0, 0};
    for (long r = (long)blockIdx.x * RPB + rsub; r < n; r += (long)gridDim.x * RPB) {
        float4 v = *(const float4*)(x + r * C + cg * 4);
        s.x += v.x; s.y += v.y; s.z += v.z; s.w += v.w;
        q.x += v.x * v.x; q.y += v.y * v.y; q.z += v.z * v.z; q.w += v.w * v.w;
    }
    __shared__ float4 sh[256], sq[256];
    sh[tid] = s; sq[tid] = q;
    __syncthreads();
    if (rsub == 0) {
        for (int j = 1; j < RPB; j++) {
            float4 t = sh[j * CG + cg];
            s.x += t.x; s.y += t.y; s.z += t.z; s.w += t.w;
            t = sq[j * CG + cg];
            q.x += t.x; q.y += t.y; q.z += t.z; q.w += t.w;
        }
        *(float4*)&part[blockIdx.x * C + cg * 4] = s;
        *(float4*)&part[NB * C + blockIdx.x * C + cg * 4] = q;
    }
}

template <int C, int CPG>
__global__ void gn_finalize(const float* __restrict__ part, const float* __restrict__ w,
                            const float* __restrict__ b, float rcount) {
    int c = threadIdx.x;
    float s = 0.f, q = 0.f;
    for (int blk = 0; blk < NB; blk++) {
        s += part[blk * C + c];
        q += part[NB * C + blk * C + c];
    }
    __shared__ float cs[256], cq[256];
    cs[c] = s; cq[c] = q;
    __syncthreads();
    __shared__ float mu[32], rs[32];
    if (c < C / CPG) {
        float S = 0.f, Q = 0.f;
        for (int j = 0; j < CPG; j++) { S += cs[c * CPG + j]; Q += cq[c * CPG + j]; }
        float m = S * rcount;
        float v = Q * rcount - m * m;
        mu[c] = m;
        rs[c] = rsqrtf(v + 1e-5f);
    }
    __syncthreads();
    int g = c / CPG;
    float sc = w[c] * rs[g];
    g_scale[c] = sc;
    g_shift[c] = b[c] - mu[g] * sc;
}

__global__ void downsample_kernel(const float* __restrict__ feats,
                                  const int* __restrict__ seg, int n) {
    long t = (long)blockIdx.x * blockDim.x + threadIdx.x;
    if (t >= (long)n * 32) return;
    int row = (int)(t >> 5);
    int q = (int)(t & 31);
    int c = q * 4;
    int s = seg[row];
    float4 f = *(const float4*)(feats + (long)row * 128 + c);
    float4 sc = *(const float4*)(g_scale + c);
    float4 sh = *(const float4*)(g_shift + c);
    float h0 = silu_f(f.x * sc.x + sh.x);
    float h1 = silu_f(f.y * sc.y + sh.y);
    float h2 = silu_f(f.z * sc.z + sh.z);
    float h3 = silu_f(f.w * sc.w + sh.w);
    float* hp = g_A + (long)s * 128 + c;
    float* xp = g_B + (long)s * 128 + c;
    atomicAdd(hp + 0, h0); atomicAdd(hp + 1, h1);
    atomicAdd(hp + 2, h2); atomicAdd(hp + 3, h3);
    atomicAdd(xp + 0, f.x); atomicAdd(xp + 1, f.y);
    atomicAdd(xp + 2, f.z); atomicAdd(xp + 3, f.w);
    if (q == 0) atomicAdd(g_cnt + s, 1.f);
}

__global__ void finalize_down(int M) {
    long t = (long)blockIdx.x * blockDim.x + threadIdx.x;
    if (t >= (long)M * 32) return;
    int row = (int)(t >> 5);
    int c = (int)(t & 31) * 4;
    float ic = 1.f / fmaxf(g_cnt[row], 1.f);
    size_t base = (size_t)row * 128 + c;
    float4 va = *(const float4*)(g_A + base);
    float4 vb = *(const float4*)(g_B + base);
    g_hd[base + 0] = __float2half(va.x * ic);
    g_hd[base + 1] = __float2half(va.y * ic);
    g_hd[base + 2] = __float2half(va.z * ic);
    g_hd[base + 3] = __float2half(va.w * ic);
    g_xd[base + 0] = __float2half(vb.x * ic);
    g_xd[base + 1] = __float2half(vb.y * ic);
    g_xd[base + 2] = __float2half(vb.z * ic);
    g_xd[base + 3] = __float2half(vb.w * ic);
}

__global__ void apply_gn2(int M) {
    long t = (long)blockIdx.x * blockDim.x + threadIdx.x;
    if (t >= (long)M * 64) return;
    int row = (int)(t >> 6);
    int c = (int)(t & 63) * 4;
    size_t base = (size_t)row * 256 + c;
    float4 v = *(const float4*)(g_C + base);
    float4 sc = *(const float4*)(g_scale + c);
    float4 sh = *(const float4*)(g_shift + c);
    g_h2[base + 0] = __float2half(silu_f(v.x * sc.x + sh.x));
    g_h2[base + 1] = __float2half(silu_f(v.y * sc.y + sh.y));
    g_h2[base + 2] = __float2half(silu_f(v.z * sc.z + sh.z));
    g_h2[base + 3] = __float2half(silu_f(v.w * sc.w + sh.w));
}

// transpose + fp16 + CHUNK/SWIZZLE: out elt = [(k*NCH+ch)*256 + n]*32 + (q^((n>>1)&3))*8 + o
template <int CIN>
__global__ void prep_w(const float* __restrict__ W, fh* __restrict__ wo, int total) {
    int idx = blockIdx.x * blockDim.x + threadIdx.x;
    int stride = gridDim.x * blockDim.x;
    const int NCH = CIN / 32;
    for (; idx < total; idx += stride) {
        int c = idx % CIN;
        int n = (idx / CIN) % 256;
        int k = idx / (CIN * 256);
        float v = W[((size_t)k * CIN + c) * 256 + n];
        int ch = c >> 5, q = (c >> 3) & 3, o = c & 7;
        size_t dst = ((size_t)(k * NCH + ch) * 256 + n) * 32 + ((q ^ ((n >> 1) & 3)) << 3) + o;
        wo[dst] = __float2half(v);
    }
}

// ---------------- HMMA gather-conv: fp16 single-plane, N-split, occ 2 -----------
// Grid = (M/64 tiles) x 2 N-halves. CTA 256 thr / 8 warps; tile 64(M) x 128(N);
// warp tile 32x32. Chunks (tap, k0=32): A 64x32 fp16 cp.async (zero-fill for
// missing rows, 4KB); B 128x32 fp16 via 1 bulk copy of pre-swizzled block (8KB).
// 4 stages, issue(i+3) after the single per-chunk __syncthreads.
// SMEM: A 4x4KB @0, B 4x8KB @16384, mbars @49152, nid @49184.
static constexpr int CONV_SMEM = 49184 + 28 * 64 * 4;

template <int CIN, bool FUSE_SKIP>
__global__ __launch_bounds__(256, 2) void conv_hmma(
    const fh* __restrict__ x, const fh* __restrict__ w,
    const fh* __restrict__ sx, const fh* __restrict__ sw,
    const float* __restrict__ bias, const float* __restrict__ bias2,
    const int* __restrict__ nbr, float* __restrict__ out, int M) {
    extern __shared__ char smem[];
    constexpr int NCH = CIN / 32;
    constexpr int NREG = 27 * NCH;
    constexpr int TC = NREG + (FUSE_SKIP ? 4 : 0);
    constexpr int NT = FUSE_SKIP ? 28 : 27;
    const uint32_t sbase = smem_u32(smem);
    const uint32_t mbars = sbase + 49152;
    int* nid = (int*)(smem + 49184);
    const int tid = threadIdx.x;
    const int mbase = (blockIdx.x >> 1) * 64;
    const int n0 = (blockIdx.x & 1) * 128;
    const int lane = tid & 31;
    const int wm = (tid >> 5) >> 2;   // 0..1
    const int wn = (tid >> 5) & 3;    // 0..3

    if (tid == 0) {
        MBARRIER_INIT(mbars + 0, 1);
        MBARRIER_INIT(mbars + 8, 1);
        MBARRIER_INIT(mbars + 16, 1);
        MBARRIER_INIT(mbars + 24, 1);
    }
    for (int u = tid; u < NT * 64; u += 256) {
        int tap = u >> 6;
        int r = mbase + (u & 63);
        nid[u] = (tap == 27) ? ((r < M) ? r : -1)
                             : ((r < M) ? nbr[(size_t)r * 27 + tap] : -1);
    }
    __syncthreads();

    float d[2][4][4];
#pragma unroll
    for (int a = 0; a < 2; a++)
#pragma unroll
        for (int b = 0; b < 4; b++)
#pragma unroll
            for (int c = 0; c < 4; c++) d[a][b][c] = 0.f;

    // issue chunk i: A via cp.async (256 pieces, 1/thread); B via 1 bulk copy
    auto issueC = [&](int i) {
        int tap, c0, cin, ch;
        const fh *ax, *bw;
        if (i < NREG) {
            tap = i / NCH; ch = i % NCH; c0 = ch * 32; cin = CIN;
            ax = x;
            bw = w + (size_t)(tap * NCH + ch) * 8192 + n0 * 32;
        } else {
            tap = 27; ch = i - NREG; c0 = ch * 32; cin = 128;
            ax = sx;
            bw = sw + (size_t)ch * 8192 + n0 * 32;
        }
        const int* nt = nid + tap * 64;
        const uint32_t ab = sbase + (i & 3) * 4096;
        const uint32_t bb = sbase + 16384 + (i & 3) * 8192;
        if (tid == 0) {
            FENCE_ASYNC();
            MBAR_ARRIVE_EXPECT(mbars + (i & 3) * 8, 8192u);
            cp_bulk_g2s(bb, bw, 8192u, mbars + (i & 3) * 8);
        }
        {
            int r = tid >> 2, q = tid & 3;
            int src = nt[r];
            const fh* sp = (src >= 0) ? (ax + (size_t)src * cin + c0 + q * 8)
                                      : (const fh*)g_zrow;
            cp_async16z(ab + r * 64 + ((q ^ ((r >> 1) & 3)) << 4),
                        sp, (src >= 0) ? 16u : 0u);
        }
        cp_commit();
    };

    issueC(0);
    if (TC > 1) issueC(1);
    if (TC > 2) issueC(2);

    for (int i = 0; i < TC; i++) {
        int newest = (TC - 1 < i + 2) ? (TC - 1) : (i + 2);
        int ahead = newest - i;
        if (ahead >= 2) cp_wait2();
        else if (ahead == 1) cp_wait1();
        else cp_wait0();
        MBARRIER_WAIT_PARITY(mbars + (i & 3) * 8, (i >> 2) & 1);
        __syncthreads();
        if (i + 3 < TC) issueC(i + 3);   // writes buf (i-1)&3: drained by sync

        const uint32_t ab = sbase + (i & 3) * 4096;
        const uint32_t bb = sbase + 16384 + (i & 3) * 8192;
#pragma unroll
        for (int ks = 0; ks < 2; ks++) {
            uint32_t ah[2][4];
            const int u = ks * 2 + ((lane >> 4) & 1);
#pragma unroll
            for (int mt = 0; mt < 2; mt++) {
                int row = wm * 32 + mt * 16 + (lane & 15);
                ldmx4(ah[mt], ab + row * 64 + ((u ^ ((row >> 1) & 3)) << 4));
            }
            const int brow = (lane & 7) + ((lane & 16) ? 8 : 0);
            const int bu = ks * 2 + ((lane >> 3) & 1);
#pragma unroll
            for (int p = 0; p < 2; p++) {
                int nl = wn * 32 + p * 16 + brow;   // local col in [0,128)
                uint32_t bh[4];
                ldmx4(bh, bb + nl * 64 + ((bu ^ ((nl >> 1) & 3)) << 4));
#pragma unroll
                for (int mt = 0; mt < 2; mt++) {
                    mma16816(d[mt][2 * p + 0], ah[mt], &bh[0]);
                    mma16816(d[mt][2 * p + 1], ah[mt], &bh[2]);
                }
            }
        }
    }

    // epilogue: direct global stores
#pragma unroll
    for (int mt = 0; mt < 2; mt++) {
        int r0 = mbase + wm * 32 + mt * 16 + lane / 4;
#pragma unroll
        for (int t = 0; t < 4; t++) {
            int gc = n0 + wn * 32 + t * 8 + (lane % 4) * 2;
            float bx = bias[gc], by = bias[gc + 1];
            if (FUSE_SKIP) { bx += bias2[gc]; by += bias2[gc + 1]; }
            if (r0 < M) {
                float2 v = {d[mt][t][0] + bx, d[mt][t][1] + by};
                *(float2*)(out + (size_t)r0 * 256 + gc) = v;
            }
            if (r0 + 8 < M) {
                float2 v = {d[mt][t][2] + bx, d[mt][t][3] + by};
                *(float2*)(out + (size_t)(r0 + 8) * 256 + gc) = v;
            }
        }
    }
}

// ---------------- launch ----------------
extern "C" void kernel_launch(void* const* d_in, const int* in_sizes, int n_in,
                              void* d_out, int out_size) {
    const float* feats = (const float*)d_in[0];
    const float* gn1_w = (const float*)d_in[1];
    const float* gn1_b = (const float*)d_in[2];
    const float* W1    = (const float*)d_in[3];
    const float* b1    = (const float*)d_in[4];
    const float* gn2_w = (const float*)d_in[5];
    const float* gn2_b = (const float*)d_in[6];
    const float* W2    = (const float*)d_in[7];
    const float* b2    = (const float*)d_in[8];
    const float* Wskip = (const float*)d_in[9];
    const float* bskip = (const float*)d_in[10];
    const int* pool_seg = (const int*)d_in[11];
    const int* nbr_idx  = (const int*)d_in[12];
    float* out = (float*)d_out;

    int N = in_sizes[0] / 128;
    int M = in_sizes[12] / 27;

    float *A, *B, *C, *cnt, *part;
    cudaGetSymbolAddress((void**)&A, g_A);
    cudaGetSymbolAddress((void**)&B, g_B);
    cudaGetSymbolAddress((void**)&C, g_C);
    cudaGetSymbolAddress((void**)&cnt, g_cnt);
    cudaGetSymbolAddress((void**)&part, g_part);
    fh *hd, *xd, *h2, *W1p, *W2p, *WSp;
    cudaGetSymbolAddress((void**)&hd, g_hd);
    cudaGetSymbolAddress((void**)&xd, g_xd);
    cudaGetSymbolAddress((void**)&h2, g_h2);
    cudaGetSymbolAddress((void**)&W1p, g_W1);
    cudaGetSymbolAddress((void**)&W2p, g_W2);
    cudaGetSymbolAddress((void**)&WSp, g_WS);

    cudaFuncSetAttribute(conv_hmma<128, false>,
                         cudaFuncAttributeMaxDynamicSharedMemorySize, CONV_SMEM);
    cudaFuncSetAttribute(conv_hmma<256, true>,
                         cudaFuncAttributeMaxDynamicSharedMemorySize, CONV_SMEM);

    // zero atomic accumulators (graph replays -> re-zero every launch)
    zero_kernel<<<4096, 256>>>(A, (size_t)M * 128);
    zero_kernel<<<4096, 256>>>(B, (size_t)M * 128);
    zero_kernel<<<256, 256>>>(cnt, (size_t)M);

    // weight transpose + fp16 + chunked/pre-swizzled layout
    prep_w<128><<<1024, 256>>>(W1, W1p, 27 * 256 * 128);
    prep_w<256><<<2048, 256>>>(W2, W2p, 27 * 256 * 256);
    prep_w<128><<<128, 256>>>(Wskip, WSp, 256 * 128);

    // GN1 stats + finalize
    gn_stats<128><<<NB, 256>>>(feats, N, part);
    gn_finalize<128, 4><<<1, 128>>>(part, gn1_w, gn1_b, 1.f / ((float)N * 4.f));

    // GN1 apply + SiLU + segment sums; then means -> fp16 planes
    long dthreads = (long)N * 32;
    downsample_kernel<<<(int)((dthreads + 255) / 256), 256>>>(feats, pool_seg, N);
    long fthreads = (long)M * 32;
    finalize_down<<<(int)((fthreads + 255) / 256), 256>>>(M);

    int nconv = ((M + 63) / 64) * 2;   // x2 N-halves

    // conv1: h1 = conv(h_d, W1) + b1
    conv_hmma<128, false><<<nconv, 256, CONV_SMEM>>>(
        hd, W1p, nullptr, nullptr, b1, nullptr, nbr_idx, C, M);

    // GN2 stats + finalize + apply (emits h2 fp16 plane)
    gn_stats<256><<<NB, 256>>>(C, M, part);
    gn_finalize<256, 8><<<1, 256>>>(part, gn2_w, gn2_b, 1.f / ((float)M * 8.f));
    long athreads = (long)M * 64;
    apply_gn2<<<(int)((athreads + 255) / 256), 256>>>(M);

    // conv2 + fused skip: out = conv(h2, W2) + b2 + x_d @ Wskip + bskip
    conv_hmma<256, true><<<nconv, 256, CONV_SMEM>>>(
        h2, W2p, xd, WSp, b2, bskip, nbr_idx, out, M);
}